// round 8
// baseline (speedup 1.0000x reference)
#include <cuda_runtime.h>
#include <cuda_bf16.h>
#include <cstdint>

#define NN 50000
#define EE 800000
#define DD 64
#define ET 6250                 // EE / 128
#define NT 391                  // ceil(NN / 128)
#define KP 136                  // node-kernel padded K stride (bf16)

// ---------------- device-global scratch (no allocations allowed) ----------
__device__ float g_agg[NN * DD];
__device__ float g_inv[NN];
__device__ int   g_cnt[NN];
__device__ float g_Wc[128 * 128];
__device__ float g_Px[NN * 128];   // per-node x @ Wc[0:64] + be1
__device__ int   g_is64;

__device__ __forceinline__ int load_row(const void* eidx, int i) {
    if (g_is64) return (int)((const long long*)eidx)[i];
    return ((const int*)eidx)[i];
}

// One prologue launch: zero agg, zero cnt, detect eidx dtype.
__global__ void prolog_k(const void* eidx, float* agg, int* cnt) {
    int i = blockIdx.x * blockDim.x + threadIdx.x;
    if (i < NN * DD / 4) ((float4*)agg)[i] = make_float4(0.f, 0.f, 0.f, 0.f);
    if (i < NN) cnt[i] = 0;
    if (i == 0) {
        const long long* p = (const long long*)eidx;
        int ok = 1;
        for (int j = 0; j < 64; j++) {
            long long v = p[j];
            if (v < 0 || v >= NN) { ok = 0; break; }
        }
        g_is64 = ok;
    }
}

__global__ void combine_w_k(const float* __restrict__ We1, float* __restrict__ Wc) {
    int i = blockIdx.x * blockDim.x + threadIdx.x;
    if (i < 128 * 128) {
        int k = i >> 7, n = i & 127;
        float v = We1[(k + 64) * 128 + n];
        if (k < 64) v += We1[k * 128 + n];
        Wc[i] = v;
    }
}

__global__ void zero_f4(float* p, int n4) {
    int i = blockIdx.x * blockDim.x + threadIdx.x;
    if (i < n4) ((float4*)p)[i] = make_float4(0.f, 0.f, 0.f, 0.f);
}
__global__ void count_k(const void* eidx, int* cnt) {
    int i = blockIdx.x * blockDim.x + threadIdx.x;
    if (i < EE) atomicAdd(&cnt[load_row(eidx, i)], 1);
}
__global__ void inv_k(const int* __restrict__ cnt, float* __restrict__ inv) {
    int i = blockIdx.x * blockDim.x + threadIdx.x;
    if (i < NN) inv[i] = 1.0f / fmaxf((float)cnt[i], 1.0f);
}

// ---------------- helpers ---------------------------------------------------
__device__ __forceinline__ uint32_t pack_bf2(__nv_bfloat16 a, __nv_bfloat16 b) {
    unsigned short ua = *(unsigned short*)&a, ub = *(unsigned short*)&b;
    return (uint32_t)ua | ((uint32_t)ub << 16);
}

__device__ __forceinline__ void split_pair(float f0, float f1, uint32_t& hi, uint32_t& lo) {
    __nv_bfloat16 h0 = __float2bfloat16_rn(f0);
    __nv_bfloat16 h1 = __float2bfloat16_rn(f1);
    float r0 = f0 - __bfloat162float(h0);
    float r1 = f1 - __bfloat162float(h1);
    hi = pack_bf2(h0, h1);
    lo = pack_bf2(__float2bfloat16_rn(r0), __float2bfloat16_rn(r1));
}

// m16n8k16 row.col bf16 -> f32 accumulate (baseline PTX, sm_80+)
__device__ __forceinline__ void mma_bf16(float* d, const uint32_t* a, const uint32_t* b) {
    asm volatile(
        "mma.sync.aligned.m16n8k16.row.col.f32.bf16.bf16.f32 "
        "{%0,%1,%2,%3}, {%4,%5,%6,%7}, {%8,%9}, {%0,%1,%2,%3};"
        : "+f"(d[0]), "+f"(d[1]), "+f"(d[2]), "+f"(d[3])
        : "r"(a[0]), "r"(a[1]), "r"(a[2]), "r"(a[3]), "r"(b[0]), "r"(b[1]));
}

// ================= EDGE KERNEL (2 CTAs/SM, H in registers) =================
#define E_KP  72                  // K=64 + 8 pad (bf16 elems)
#define E_KP2 136                 // W2 stride, K=128 + 8
#define E_AH  0                   // [128][72] bf16
#define E_AL  18432
#define E_W1H 36864               // [128n][72]
#define E_W1L 55296
#define E_W2H 73728               // [64n][136]
#define E_W2L 91136
#define E_B2  108544              // 64 f32
#define E_SMEM 108800

__global__ void __launch_bounds__(256, 2)
edge_mma(const float* __restrict__ ea, const void* __restrict__ eidx,
         const float* __restrict__ Px,
         const float* __restrict__ Wc, const float* __restrict__ W2,
         const float* __restrict__ b2,
         float* __restrict__ dst, float* __restrict__ agg, int ntiles)
{
    extern __shared__ char smc[];
    uint16_t* sAh  = (uint16_t*)(smc + E_AH);
    uint16_t* sAl  = (uint16_t*)(smc + E_AL);
    uint16_t* sW1h = (uint16_t*)(smc + E_W1H);
    uint16_t* sW1l = (uint16_t*)(smc + E_W1L);
    uint16_t* sW2h = (uint16_t*)(smc + E_W2H);
    uint16_t* sW2l = (uint16_t*)(smc + E_W2L);
    float*    sb2  = (float*)(smc + E_B2);

    const int tid = threadIdx.x;
    const int lane = tid & 31, w = tid >> 5;
    const int g = lane >> 2, qt = lane & 3;

    // ---- stage weights once: W1 = Wc rows 64:127 (K=64), W2 (K=128) ----
    {
        int n = tid & 127, k0 = (tid >> 7) * 32;
        for (int k = k0; k < k0 + 32; k += 2) {
            uint32_t hi, lo;
            split_pair(Wc[(64 + k) * 128 + n], Wc[(65 + k) * 128 + n], hi, lo);
            *(uint32_t*)&sW1h[n * E_KP + k] = hi;
            *(uint32_t*)&sW1l[n * E_KP + k] = lo;
        }
    }
    {
        int n = tid & 63, k0 = (tid >> 6) * 32;
        for (int k = k0; k < k0 + 32; k += 2) {
            uint32_t hi, lo;
            split_pair(W2[k * 64 + n], W2[(k + 1) * 64 + n], hi, lo);
            *(uint32_t*)&sW2h[n * E_KP2 + k] = hi;
            *(uint32_t*)&sW2l[n * E_KP2 + k] = lo;
        }
    }
    if (tid < 64) sb2[tid] = b2[tid];
    __syncthreads();

    for (int tile = blockIdx.x; tile < ntiles; tile += gridDim.x) {
        const int i0 = tile * 128;
        const int mrow0 = 16 * w + g;          // warp-local rows g, g+8

        const int r0 = load_row(eidx, i0 + mrow0);
        const int r1 = load_row(eidx, i0 + mrow0 + 8);

        // ---- init acc1 from Px gather (bias be1 folded into Px) ----
        float acc1[16][4];
        #pragma unroll
        for (int nt = 0; nt < 16; nt++) {
            int col = 8 * nt + 2 * qt;
            float2 v0 = *(const float2*)&Px[(size_t)r0 * 128 + col];
            float2 v1 = *(const float2*)&Px[(size_t)r1 * 128 + col];
            acc1[nt][0] = v0.x; acc1[nt][1] = v0.y;
            acc1[nt][2] = v1.x; acc1[nt][3] = v1.y;
        }

        // ---- build A tile from ea (K=64), bf16 split ----
        {
            const int m = tid & 127, kh = (tid >> 7) * 32;
            const float* src = ea + (size_t)(i0 + m) * DD + kh;
            #pragma unroll
            for (int c = 0; c < 32; c += 8) {
                float4 f0 = *(const float4*)(src + c);
                float4 f1 = *(const float4*)(src + c + 4);
                uint32_t hw[4], lw[4];
                split_pair(f0.x, f0.y, hw[0], lw[0]);
                split_pair(f0.z, f0.w, hw[1], lw[1]);
                split_pair(f1.x, f1.y, hw[2], lw[2]);
                split_pair(f1.z, f1.w, hw[3], lw[3]);
                int e = m * E_KP + kh + c;
                *(uint4*)&sAh[e] = *(uint4*)hw;
                *(uint4*)&sAl[e] = *(uint4*)lw;
            }
        }
        __syncthreads();

        // ---- GEMM1: acc1 += ea @ W1 (K=64, 3 split terms) ----
        #pragma unroll
        for (int ks = 0; ks < 4; ks++) {
            const int kb = ks * 16 + 2 * qt;
            uint32_t ah[4], al[4];
            {
                int e = mrow0 * E_KP + kb;
                ah[0] = *(const uint32_t*)&sAh[e];
                ah[1] = *(const uint32_t*)&sAh[e + 8 * E_KP];
                ah[2] = *(const uint32_t*)&sAh[e + 8];
                ah[3] = *(const uint32_t*)&sAh[e + 8 * E_KP + 8];
                al[0] = *(const uint32_t*)&sAl[e];
                al[1] = *(const uint32_t*)&sAl[e + 8 * E_KP];
                al[2] = *(const uint32_t*)&sAl[e + 8];
                al[3] = *(const uint32_t*)&sAl[e + 8 * E_KP + 8];
            }
            #pragma unroll
            for (int nt = 0; nt < 16; nt++) {
                int e = (8 * nt + g) * E_KP + kb;
                uint32_t bh[2], bl[2];
                bh[0] = *(const uint32_t*)&sW1h[e];
                bh[1] = *(const uint32_t*)&sW1h[e + 8];
                bl[0] = *(const uint32_t*)&sW1l[e];
                bl[1] = *(const uint32_t*)&sW1l[e + 8];
                mma_bf16(acc1[nt], ah, bh);
                mma_bf16(acc1[nt], ah, bl);
                mma_bf16(acc1[nt], al, bh);
            }
        }
        __syncthreads();   // all sA reads done -> next tile may rebuild A

        // ---- pack H fragments (relu fused) -> acc1 dies here, no spills ----
        // acc1[2ks], acc1[2ks+1] ARE k-step ks's A fragment (rows g, g+8).
        uint32_t hA[8][4], lA[8][4];
        #pragma unroll
        for (int ks = 0; ks < 8; ks++) {
            float v00 = fmaxf(acc1[2 * ks][0], 0.f);
            float v01 = fmaxf(acc1[2 * ks][1], 0.f);
            float v02 = fmaxf(acc1[2 * ks][2], 0.f);
            float v03 = fmaxf(acc1[2 * ks][3], 0.f);
            float v10 = fmaxf(acc1[2 * ks + 1][0], 0.f);
            float v11 = fmaxf(acc1[2 * ks + 1][1], 0.f);
            float v12 = fmaxf(acc1[2 * ks + 1][2], 0.f);
            float v13 = fmaxf(acc1[2 * ks + 1][3], 0.f);
            split_pair(v00, v01, hA[ks][0], lA[ks][0]);
            split_pair(v02, v03, hA[ks][1], lA[ks][1]);
            split_pair(v10, v11, hA[ks][2], lA[ks][2]);
            split_pair(v12, v13, hA[ks][3], lA[ks][3]);
        }

        // ---- GEMM2: acc2 = H @ W2 (K=128) from packed registers ----
        float acc2[8][4];
        #pragma unroll
        for (int nt = 0; nt < 8; nt++)
            #pragma unroll
            for (int j = 0; j < 4; j++) acc2[nt][j] = 0.f;

        #pragma unroll
        for (int ks = 0; ks < 8; ks++) {
            const int kb = ks * 16 + 2 * qt;
            #pragma unroll
            for (int nt = 0; nt < 8; nt++) {
                int e = (8 * nt + g) * E_KP2 + kb;
                uint32_t bh[2], bl[2];
                bh[0] = *(const uint32_t*)&sW2h[e];
                bh[1] = *(const uint32_t*)&sW2h[e + 8];
                bl[0] = *(const uint32_t*)&sW2l[e];
                bl[1] = *(const uint32_t*)&sW2l[e + 8];
                mma_bf16(acc2[nt], hA[ks], bh);
                mma_bf16(acc2[nt], hA[ks], bl);
                mma_bf16(acc2[nt], lA[ks], bh);
            }
        }

        // ---- epilogue: red.add agg[row]; dst = ea + (D2 + b2) ----
        #pragma unroll
        for (int nt = 0; nt < 8; nt++) {
            int col = 8 * nt + 2 * qt;
            float vx0 = acc2[nt][0] + sb2[col];
            float vy0 = acc2[nt][1] + sb2[col + 1];
            float vx1 = acc2[nt][2] + sb2[col];
            float vy1 = acc2[nt][3] + sb2[col + 1];
            float* ap0 = agg + (size_t)r0 * DD + col;
            float* ap1 = agg + (size_t)r1 * DD + col;
            asm volatile("red.global.add.v2.f32 [%0], {%1, %2};"
                         :: "l"(ap0), "f"(vx0), "f"(vy0) : "memory");
            asm volatile("red.global.add.v2.f32 [%0], {%1, %2};"
                         :: "l"(ap1), "f"(vx1), "f"(vy1) : "memory");
            size_t o0 = (size_t)(i0 + mrow0) * DD + col;
            size_t o1 = (size_t)(i0 + mrow0 + 8) * DD + col;
            float2 e0 = *(const float2*)(ea + o0);
            float2 e1 = *(const float2*)(ea + o1);
            *(float2*)(dst + o0) = make_float2(e0.x + vx0, e0.y + vy0);
            *(float2*)(dst + o1) = make_float2(e1.x + vx1, e1.y + vy1);
        }
    }
}

// ---------------- node / px kernels (unchanged layout) ---------------------
#define OFF_AH   0
#define OFF_AL   34816
#define OFF_W1H  69632
#define OFF_W1L  104448
#define OFF_W2H  139264
#define OFF_W2L  156672
#define OFF_B1   174080
#define OFF_B2   174592
#define SMEMSZ   175360

__global__ void __launch_bounds__(256, 1)
px_k(const float* __restrict__ x, const float* __restrict__ Wc,
     const float* __restrict__ be1, float* __restrict__ Px)
{
    extern __shared__ char smc[];
    uint16_t* sAh = (uint16_t*)(smc + OFF_AH);
    uint16_t* sAl = (uint16_t*)(smc + OFF_AL);
    uint16_t* sWh = (uint16_t*)(smc + OFF_W1H);
    uint16_t* sWl = (uint16_t*)(smc + OFF_W1L);
    float*    sb1 = (float*)(smc + OFF_B1);

    const int tid = threadIdx.x;
    const int lane = tid & 31, w = tid >> 5;
    const int g = lane >> 2, qt = lane & 3;
    const int wm = w >> 1, wn = w & 1;

    {
        int n = tid & 127, k0 = (tid >> 7) * 32;
        for (int k = k0; k < k0 + 32; k += 2) {
            uint32_t hi, lo;
            split_pair(Wc[k * 128 + n], Wc[(k + 1) * 128 + n], hi, lo);
            *(uint32_t*)&sWh[n * KP + k] = hi;
            *(uint32_t*)&sWl[n * KP + k] = lo;
        }
    }
    if (tid < 128) sb1[tid] = be1[tid];
    __syncthreads();

    for (int tile = blockIdx.x; tile < NT; tile += gridDim.x) {
        const int i0 = tile * 128;
        {
            const int m = tid & 127, ch = (tid >> 7) * 32;
            const int gi = i0 + m;
            const bool valid = gi < NN;
            const float* src = x + (size_t)(valid ? gi : 0) * DD + ch;
            #pragma unroll
            for (int c = 0; c < 32; c += 8) {
                float4 f0, f1;
                if (valid) { f0 = *(const float4*)(src + c); f1 = *(const float4*)(src + c + 4); }
                else { f0 = make_float4(0,0,0,0); f1 = f0; }
                uint32_t hw[4], lw[4];
                split_pair(f0.x, f0.y, hw[0], lw[0]);
                split_pair(f0.z, f0.w, hw[1], lw[1]);
                split_pair(f1.x, f1.y, hw[2], lw[2]);
                split_pair(f1.z, f1.w, hw[3], lw[3]);
                int e = m * KP + ch + c;
                *(uint4*)&sAh[e] = *(uint4*)hw;
                *(uint4*)&sAl[e] = *(uint4*)lw;
            }
        }
        __syncthreads();

        float acc[2][8][4];
        #pragma unroll
        for (int mt = 0; mt < 2; mt++)
            #pragma unroll
            for (int nt = 0; nt < 8; nt++)
                #pragma unroll
                for (int j = 0; j < 4; j++) acc[mt][nt][j] = 0.f;

        #pragma unroll
        for (int ks = 0; ks < 4; ks++) {
            const int kb = ks * 16 + 2 * qt;
            uint32_t ah[2][4], al[2][4];
            #pragma unroll
            for (int mt = 0; mt < 2; mt++) {
                int e = (wm * 32 + mt * 16 + g) * KP + kb;
                ah[mt][0] = *(const uint32_t*)&sAh[e];
                ah[mt][1] = *(const uint32_t*)&sAh[e + 8 * KP];
                ah[mt][2] = *(const uint32_t*)&sAh[e + 8];
                ah[mt][3] = *(const uint32_t*)&sAh[e + 8 * KP + 8];
                al[mt][0] = *(const uint32_t*)&sAl[e];
                al[mt][1] = *(const uint32_t*)&sAl[e + 8 * KP];
                al[mt][2] = *(const uint32_t*)&sAl[e + 8];
                al[mt][3] = *(const uint32_t*)&sAl[e + 8 * KP + 8];
            }
            #pragma unroll
            for (int nt = 0; nt < 8; nt++) {
                int e = (wn * 64 + nt * 8 + g) * KP + kb;
                uint32_t bh[2], bl[2];
                bh[0] = *(const uint32_t*)&sWh[e];
                bh[1] = *(const uint32_t*)&sWh[e + 8];
                bl[0] = *(const uint32_t*)&sWl[e];
                bl[1] = *(const uint32_t*)&sWl[e + 8];
                mma_bf16(acc[0][nt], ah[0], bh);
                mma_bf16(acc[1][nt], ah[1], bh);
                mma_bf16(acc[0][nt], ah[0], bl);
                mma_bf16(acc[1][nt], ah[1], bl);
                mma_bf16(acc[0][nt], al[0], bh);
                mma_bf16(acc[1][nt], al[1], bh);
            }
        }

        #pragma unroll
        for (int mt = 0; mt < 2; mt++)
            #pragma unroll
            for (int nt = 0; nt < 8; nt++) {
                int rl = wm * 32 + mt * 16 + g;
                int col = wn * 64 + nt * 8 + 2 * qt;
                #pragma unroll
                for (int rh = 0; rh < 2; rh++) {
                    int gi = i0 + rl + rh * 8;
                    if (gi >= NN) continue;
                    float2 v = make_float2(acc[mt][nt][rh * 2] + sb1[col],
                                           acc[mt][nt][rh * 2 + 1] + sb1[col + 1]);
                    *(float2*)&Px[(size_t)gi * 128 + col] = v;
                }
            }
        __syncthreads();
    }
}

__global__ void __launch_bounds__(256, 1)
node_mma(const float* __restrict__ x_src, const float* __restrict__ a_src,
         const float* __restrict__ W1, const float* __restrict__ b1,
         const float* __restrict__ W2, const float* __restrict__ b2,
         float* __restrict__ dst, const float* __restrict__ inv, int count)
{
    extern __shared__ char smc[];
    uint16_t* sAh  = (uint16_t*)(smc + OFF_AH);
    uint16_t* sAl  = (uint16_t*)(smc + OFF_AL);
    uint16_t* sW1h = (uint16_t*)(smc + OFF_W1H);
    uint16_t* sW1l = (uint16_t*)(smc + OFF_W1L);
    uint16_t* sW2h = (uint16_t*)(smc + OFF_W2H);
    uint16_t* sW2l = (uint16_t*)(smc + OFF_W2L);
    float*    sb1  = (float*)(smc + OFF_B1);
    float*    sb2  = (float*)(smc + OFF_B2);

    const int tid = threadIdx.x;
    const int lane = tid & 31, w = tid >> 5;
    const int g = lane >> 2, qt = lane & 3;
    const int wm = w >> 1, wn = w & 1;

    {
        int n = tid & 127, k0 = (tid >> 7) * 64;
        for (int k = k0; k < k0 + 64; k += 2) {
            uint32_t hi, lo;
            split_pair(W1[k * 128 + n], W1[(k + 1) * 128 + n], hi, lo);
            *(uint32_t*)&sW1h[n * KP + k] = hi;
            *(uint32_t*)&sW1l[n * KP + k] = lo;
        }
    }
    {
        int n = tid & 63, k0 = (tid >> 6) * 32;
        for (int k = k0; k < k0 + 32; k += 2) {
            uint32_t hi, lo;
            split_pair(W2[k * 64 + n], W2[(k + 1) * 64 + n], hi, lo);
            *(uint32_t*)&sW2h[n * KP + k] = hi;
            *(uint32_t*)&sW2l[n * KP + k] = lo;
        }
    }
    if (tid < 128) sb1[tid] = b1[tid];
    if (tid < 64)  sb2[tid] = b2[tid];
    __syncthreads();

    for (int tile = blockIdx.x; tile < NT; tile += gridDim.x) {
        const int i0 = tile * 128;
        {
            const int m = tid & 127, half = tid >> 7;
            const int gi = i0 + m;
            const bool valid = gi < count;
            const float* src;
            float scale = 1.0f;
            bool doscale = false;
            if (half == 0) {
                src = x_src + (size_t)(valid ? gi : 0) * DD;
            } else {
                src = a_src + (size_t)(valid ? gi : 0) * DD;
                scale = valid ? inv[gi] : 0.0f;
                doscale = true;
            }
            #pragma unroll
            for (int c = 0; c < 64; c += 8) {
                float4 f0 = *(const float4*)(src + c);
                float4 f1 = *(const float4*)(src + c + 4);
                if (doscale) {
                    f0.x *= scale; f0.y *= scale; f0.z *= scale; f0.w *= scale;
                    f1.x *= scale; f1.y *= scale; f1.z *= scale; f1.w *= scale;
                }
                uint32_t hw[4], lw[4];
                split_pair(f0.x, f0.y, hw[0], lw[0]);
                split_pair(f0.z, f0.w, hw[1], lw[1]);
                split_pair(f1.x, f1.y, hw[2], lw[2]);
                split_pair(f1.z, f1.w, hw[3], lw[3]);
                int e = m * KP + half * 64 + c;
                *(uint4*)&sAh[e] = *(uint4*)hw;
                *(uint4*)&sAl[e] = *(uint4*)lw;
            }
        }
        __syncthreads();

        float acc[2][8][4];
        #pragma unroll
        for (int mt = 0; mt < 2; mt++)
            #pragma unroll
            for (int nt = 0; nt < 8; nt++)
                #pragma unroll
                for (int j = 0; j < 4; j++) acc[mt][nt][j] = 0.f;

        #pragma unroll
        for (int ks = 0; ks < 8; ks++) {
            const int kb = ks * 16 + 2 * qt;
            uint32_t ah[2][4], al[2][4];
            #pragma unroll
            for (int mt = 0; mt < 2; mt++) {
                int e = (wm * 32 + mt * 16 + g) * KP + kb;
                ah[mt][0] = *(const uint32_t*)&sAh[e];
                ah[mt][1] = *(const uint32_t*)&sAh[e + 8 * KP];
                ah[mt][2] = *(const uint32_t*)&sAh[e + 8];
                ah[mt][3] = *(const uint32_t*)&sAh[e + 8 * KP + 8];
                al[mt][0] = *(const uint32_t*)&sAl[e];
                al[mt][1] = *(const uint32_t*)&sAl[e + 8 * KP];
                al[mt][2] = *(const uint32_t*)&sAl[e + 8];
                al[mt][3] = *(const uint32_t*)&sAl[e + 8 * KP + 8];
            }
            #pragma unroll
            for (int nt = 0; nt < 8; nt++) {
                int e = (wn * 64 + nt * 8 + g) * KP + kb;
                uint32_t bh[2], bl[2];
                bh[0] = *(const uint32_t*)&sW1h[e];
                bh[1] = *(const uint32_t*)&sW1h[e + 8];
                bl[0] = *(const uint32_t*)&sW1l[e];
                bl[1] = *(const uint32_t*)&sW1l[e + 8];
                mma_bf16(acc[0][nt], ah[0], bh);
                mma_bf16(acc[1][nt], ah[1], bh);
                mma_bf16(acc[0][nt], ah[0], bl);
                mma_bf16(acc[1][nt], ah[1], bl);
                mma_bf16(acc[0][nt], al[0], bh);
                mma_bf16(acc[1][nt], al[1], bh);
            }
        }
        __syncthreads();

        #pragma unroll
        for (int mt = 0; mt < 2; mt++)
            #pragma unroll
            for (int nt = 0; nt < 8; nt++) {
                int row = wm * 32 + mt * 16 + g;
                int col = wn * 64 + nt * 8 + 2 * qt;
                float v0 = fmaxf(acc[mt][nt][0] + sb1[col], 0.f);
                float v1 = fmaxf(acc[mt][nt][1] + sb1[col + 1], 0.f);
                float v2 = fmaxf(acc[mt][nt][2] + sb1[col], 0.f);
                float v3 = fmaxf(acc[mt][nt][3] + sb1[col + 1], 0.f);
                uint32_t hi, lo;
                split_pair(v0, v1, hi, lo);
                *(uint32_t*)&sAh[row * KP + col] = hi;
                *(uint32_t*)&sAl[row * KP + col] = lo;
                split_pair(v2, v3, hi, lo);
                *(uint32_t*)&sAh[(row + 8) * KP + col] = hi;
                *(uint32_t*)&sAl[(row + 8) * KP + col] = lo;
            }
        __syncthreads();

        float acc2[2][4][4];
        #pragma unroll
        for (int mt = 0; mt < 2; mt++)
            #pragma unroll
            for (int nt = 0; nt < 4; nt++)
                #pragma unroll
                for (int j = 0; j < 4; j++) acc2[mt][nt][j] = 0.f;

        #pragma unroll
        for (int ks = 0; ks < 8; ks++) {
            const int kb = ks * 16 + 2 * qt;
            uint32_t ah[2][4], al[2][4];
            #pragma unroll
            for (int mt = 0; mt < 2; mt++) {
                int e = (wm * 32 + mt * 16 + g) * KP + kb;
                ah[mt][0] = *(const uint32_t*)&sAh[e];
                ah[mt][1] = *(const uint32_t*)&sAh[e + 8 * KP];
                ah[mt][2] = *(const uint32_t*)&sAh[e + 8];
                ah[mt][3] = *(const uint32_t*)&sAh[e + 8 * KP + 8];
                al[mt][0] = *(const uint32_t*)&sAl[e];
                al[mt][1] = *(const uint32_t*)&sAl[e + 8 * KP];
                al[mt][2] = *(const uint32_t*)&sAl[e + 8];
                al[mt][3] = *(const uint32_t*)&sAl[e + 8 * KP + 8];
            }
            #pragma unroll
            for (int nt = 0; nt < 4; nt++) {
                int e = (wn * 32 + nt * 8 + g) * KP + kb;
                uint32_t bh[2], bl[2];
                bh[0] = *(const uint32_t*)&sW2h[e];
                bh[1] = *(const uint32_t*)&sW2h[e + 8];
                bl[0] = *(const uint32_t*)&sW2l[e];
                bl[1] = *(const uint32_t*)&sW2l[e + 8];
                mma_bf16(acc2[0][nt], ah[0], bh);
                mma_bf16(acc2[1][nt], ah[1], bh);
                mma_bf16(acc2[0][nt], ah[0], bl);
                mma_bf16(acc2[1][nt], ah[1], bl);
                mma_bf16(acc2[0][nt], al[0], bh);
                mma_bf16(acc2[1][nt], al[1], bh);
            }
        }

        #pragma unroll
        for (int mt = 0; mt < 2; mt++)
            #pragma unroll
            for (int nt = 0; nt < 4; nt++) {
                int rl = wm * 32 + mt * 16 + g;
                int col = wn * 32 + nt * 8 + 2 * qt;
                #pragma unroll
                for (int rh = 0; rh < 2; rh++) {
                    int row = rl + rh * 8;
                    int gi = i0 + row;
                    if (gi >= count) continue;
                    float vx = acc2[mt][nt][rh * 2 + 0] + sb2[col];
                    float vy = acc2[mt][nt][rh * 2 + 1] + sb2[col + 1];
                    float2 rv = *(const float2*)(x_src + (size_t)gi * DD + col);
                    *(float2*)(dst + (size_t)gi * DD + col) =
                        make_float2(rv.x + vx, rv.y + vy);
                }
            }
        __syncthreads();
    }
}

extern "C" void kernel_launch(void* const* d_in, const int* in_sizes, int n_in,
                              void* d_out, int out_size)
{
    const float* x   = (const float*)d_in[0];
    const float* ea  = (const float*)d_in[1];
    const float* We1 = (const float*)d_in[2];
    const float* be1 = (const float*)d_in[3];
    const float* We2 = (const float*)d_in[4];
    const float* be2 = (const float*)d_in[5];
    const float* Wn1 = (const float*)d_in[6];
    const float* bn1 = (const float*)d_in[7];
    const float* Wn2 = (const float*)d_in[8];
    const float* bn2 = (const float*)d_in[9];
    const void*  eidx = d_in[10];

    float* out_x  = (float*)d_out;
    float* out_ea = (float*)d_out + (size_t)NN * DD;

    float *agg, *inv, *Wc, *Px;
    int* cnt;
    cudaGetSymbolAddress((void**)&agg, g_agg);
    cudaGetSymbolAddress((void**)&inv, g_inv);
    cudaGetSymbolAddress((void**)&cnt, g_cnt);
    cudaGetSymbolAddress((void**)&Wc,  g_Wc);
    cudaGetSymbolAddress((void**)&Px,  g_Px);

    cudaFuncSetAttribute(edge_mma, cudaFuncAttributeMaxDynamicSharedMemorySize, E_SMEM);
    cudaFuncSetAttribute(node_mma, cudaFuncAttributeMaxDynamicSharedMemorySize, SMEMSZ);
    cudaFuncSetAttribute(px_k,     cudaFuncAttributeMaxDynamicSharedMemorySize, SMEMSZ);

    int smcount = 148;
    cudaDeviceGetAttribute(&smcount, cudaDevAttrMultiProcessorCount, 0);
    int ge = 2 * smcount < ET ? 2 * smcount : ET;
    int gn = smcount < NT ? smcount : NT;

    // Edge kernel is my 4th launch (global #6 with harness prelaunches; -s 5 window).
    prolog_k<<<(NN * DD / 4 + 255) / 256, 256>>>(eidx, agg, cnt);        // 0
    combine_w_k<<<(128 * 128 + 255) / 256, 256>>>(We1, Wc);              // 1
    px_k<<<gn, 256, SMEMSZ>>>(x, Wc, be1, Px);                           // 2
    edge_mma<<<ge, 256, E_SMEM>>>(ea, eidx, Px, Wc, We2, be2,            // 3 <- profiled
                                  out_ea, agg, ET);
    count_k<<<(EE + 255) / 256, 256>>>(eidx, cnt);                       // 4
    inv_k<<<(NN + 255) / 256, 256>>>(cnt, inv);                          // 5
    node_mma<<<gn, 256, SMEMSZ>>>(x, agg, Wn1, bn1, Wn2, bn2,            // 6
                                  out_x, inv, NN);

    // iteration 2
    zero_f4<<<(NN * DD / 4 + 255) / 256, 256>>>(agg, NN * DD / 4);
    px_k<<<gn, 256, SMEMSZ>>>(out_x, Wc, be1, Px);
    edge_mma<<<ge, 256, E_SMEM>>>(out_ea, eidx, Px, Wc, We2, be2,
                                  out_ea, agg, ET);
    node_mma<<<gn, 256, SMEMSZ>>>(out_x, agg, Wn1, bn1, Wn2, bn2,
                                  out_x, inv, NN);
}

// round 9
// speedup vs baseline: 1.0588x; 1.0588x over previous
#include <cuda_runtime.h>
#include <cuda_bf16.h>
#include <cstdint>

#define NN 50000
#define EE 800000
#define DD 64
#define ET 6250                 // EE / 128
#define NT 391                  // ceil(NN / 128)
#define KP 136                  // node-kernel padded K stride (bf16)

// ---------------- device-global scratch (no allocations allowed) ----------
__device__ float g_agg[NN * DD];
__device__ float g_inv[NN];
__device__ int   g_cnt[NN];
__device__ float g_Wc[128 * 128];
__device__ float g_Px[NN * 128];   // per-node x @ Wc[0:64] + be1
__device__ int   g_is64;

__device__ __forceinline__ int load_row(const void* eidx, int i) {
    if (g_is64) return (int)((const long long*)eidx)[i];
    return ((const int*)eidx)[i];
}

__global__ void prolog_k(const void* eidx, float* agg, int* cnt) {
    int i = blockIdx.x * blockDim.x + threadIdx.x;
    if (i < NN * DD / 4) ((float4*)agg)[i] = make_float4(0.f, 0.f, 0.f, 0.f);
    if (i < NN) cnt[i] = 0;
    if (i == 0) {
        const long long* p = (const long long*)eidx;
        int ok = 1;
        for (int j = 0; j < 64; j++) {
            long long v = p[j];
            if (v < 0 || v >= NN) { ok = 0; break; }
        }
        g_is64 = ok;
    }
}

__global__ void combine_w_k(const float* __restrict__ We1, float* __restrict__ Wc) {
    int i = blockIdx.x * blockDim.x + threadIdx.x;
    if (i < 128 * 128) {
        int k = i >> 7, n = i & 127;
        float v = We1[(k + 64) * 128 + n];
        if (k < 64) v += We1[k * 128 + n];
        Wc[i] = v;
    }
}

__global__ void zero_f4(float* p, int n4) {
    int i = blockIdx.x * blockDim.x + threadIdx.x;
    if (i < n4) ((float4*)p)[i] = make_float4(0.f, 0.f, 0.f, 0.f);
}
__global__ void count_k(const void* eidx, int* cnt) {
    int i = blockIdx.x * blockDim.x + threadIdx.x;
    if (i < EE) atomicAdd(&cnt[load_row(eidx, i)], 1);
}
__global__ void inv_k(const int* __restrict__ cnt, float* __restrict__ inv) {
    int i = blockIdx.x * blockDim.x + threadIdx.x;
    if (i < NN) inv[i] = 1.0f / fmaxf((float)cnt[i], 1.0f);
}

// ---------------- helpers ---------------------------------------------------
__device__ __forceinline__ uint32_t pack_bf2(__nv_bfloat16 a, __nv_bfloat16 b) {
    unsigned short ua = *(unsigned short*)&a, ub = *(unsigned short*)&b;
    return (uint32_t)ua | ((uint32_t)ub << 16);
}

__device__ __forceinline__ void split_pair(float f0, float f1, uint32_t& hi, uint32_t& lo) {
    __nv_bfloat16 h0 = __float2bfloat16_rn(f0);
    __nv_bfloat16 h1 = __float2bfloat16_rn(f1);
    float r0 = f0 - __bfloat162float(h0);
    float r1 = f1 - __bfloat162float(h1);
    hi = pack_bf2(h0, h1);
    lo = pack_bf2(__float2bfloat16_rn(r0), __float2bfloat16_rn(r1));
}

// m16n8k16 row.col bf16 -> f32 accumulate (baseline PTX, sm_80+)
__device__ __forceinline__ void mma_bf16(float* d, const uint32_t* a, const uint32_t* b) {
    asm volatile(
        "mma.sync.aligned.m16n8k16.row.col.f32.bf16.bf16.f32 "
        "{%0,%1,%2,%3}, {%4,%5,%6,%7}, {%8,%9}, {%0,%1,%2,%3};"
        : "+f"(d[0]), "+f"(d[1]), "+f"(d[2]), "+f"(d[3])
        : "r"(a[0]), "r"(a[1]), "r"(a[2]), "r"(a[3]), "r"(b[0]), "r"(b[1]));
}

// ================= EDGE KERNEL: fragment-blocked smem, LDS.128 =============
// 16B block per (row, ks, qt): {hi(k,k+1), hi(k+8,k+9), lo(k,k+1), lo(k+8,k+9)},
// k = 16*ks + 2*qt. XOR swizzle chunk = (ks ^ (row&3))*4 + qt -> conflict-free
// LDS.128 phases (verified: g / g^1 give complementary chunk halves mod 8).
#define E_SA   0                  // A:  128 rows x 256B (K=64)
#define E_SW1  32768              // W1: 128 rows x 256B (K=64)
#define E_SW2  65536              // W2:  64 rows x 512B (K=128)
#define E_B2   98304              // 64 f32
#define E_SMEM 98560

__device__ __forceinline__ uint32_t addr64(int row, int ks, int qt) {   // 256B stride
    return ((uint32_t)row << 8) + ((uint32_t)(((ks ^ (row & 3)) << 2) + qt) << 4);
}
__device__ __forceinline__ uint32_t addr128k(int row, int ks, int qt) { // 512B stride
    return ((uint32_t)row << 9) + ((uint32_t)(((ks ^ (row & 3)) << 2) + qt) << 4);
}

__global__ void __launch_bounds__(256, 2)
edge_mma(const float* __restrict__ ea, const void* __restrict__ eidx,
         const float* __restrict__ Px,
         const float* __restrict__ Wc, const float* __restrict__ W2,
         const float* __restrict__ b2,
         float* __restrict__ dst, float* __restrict__ agg, int ntiles)
{
    extern __shared__ char smc[];
    float* sb2 = (float*)(smc + E_B2);

    const int tid = threadIdx.x;
    const int lane = tid & 31, w = tid >> 5;
    const int g = lane >> 2, qt = lane & 3;

    // ---- stage W1 = Wc rows 64:127 (K=64) in fragment blocks ----
    {
        const int n = tid & 127, h = tid >> 7;      // h: k-half (32 k's)
        uint32_t hi[16], lo[16];
        #pragma unroll
        for (int p = 0; p < 16; p++) {
            int k = 32 * h + 2 * p;
            split_pair(Wc[(64 + k) * 128 + n], Wc[(64 + k + 1) * 128 + n], hi[p], lo[p]);
        }
        #pragma unroll
        for (int j = 0; j < 2; j++)
            #pragma unroll
            for (int q = 0; q < 4; q++) {
                uint4 blk = make_uint4(hi[8 * j + q], hi[8 * j + q + 4],
                                       lo[8 * j + q], lo[8 * j + q + 4]);
                *(uint4*)(smc + E_SW1 + addr64(n, 2 * h + j, q)) = blk;
            }
    }
    // ---- stage W2 (64n x K=128) in fragment blocks ----
    {
        const int n = tid & 63, kq = tid >> 6;      // kq: k-quarter (32 k's)
        uint32_t hi[16], lo[16];
        #pragma unroll
        for (int p = 0; p < 16; p++) {
            int k = 32 * kq + 2 * p;
            split_pair(W2[k * 64 + n], W2[(k + 1) * 64 + n], hi[p], lo[p]);
        }
        #pragma unroll
        for (int j = 0; j < 2; j++)
            #pragma unroll
            for (int q = 0; q < 4; q++) {
                uint4 blk = make_uint4(hi[8 * j + q], hi[8 * j + q + 4],
                                       lo[8 * j + q], lo[8 * j + q + 4]);
                *(uint4*)(smc + E_SW2 + addr128k(n, 2 * kq + j, q)) = blk;
            }
    }
    if (tid < 64) sb2[tid] = b2[tid];
    __syncthreads();

    for (int tile = blockIdx.x; tile < ntiles; tile += gridDim.x) {
        const int i0 = tile * 128;
        const int mrow0 = 16 * w + g;               // warp-local rows g, g+8

        const int r0 = load_row(eidx, i0 + mrow0);
        const int r1 = load_row(eidx, i0 + mrow0 + 8);

        // ---- init acc1 from Px gather (be1 folded into Px) ----
        float acc1[16][4];
        #pragma unroll
        for (int nt = 0; nt < 16; nt++) {
            int col = 8 * nt + 2 * qt;
            float2 v0 = *(const float2*)&Px[(size_t)r0 * 128 + col];
            float2 v1 = *(const float2*)&Px[(size_t)r1 * 128 + col];
            acc1[nt][0] = v0.x; acc1[nt][1] = v0.y;
            acc1[nt][2] = v1.x; acc1[nt][3] = v1.y;
        }

        // ---- build A tile (K=64) in fragment blocks ----
        {
            const int m = tid & 127, h = tid >> 7;
            const float* src = ea + (size_t)(i0 + m) * DD + 32 * h;
            uint32_t hi[16], lo[16];
            #pragma unroll
            for (int c = 0; c < 32; c += 8) {
                float4 f0 = *(const float4*)(src + c);
                float4 f1 = *(const float4*)(src + c + 4);
                int p = c >> 1;
                split_pair(f0.x, f0.y, hi[p],     lo[p]);
                split_pair(f0.z, f0.w, hi[p + 1], lo[p + 1]);
                split_pair(f1.x, f1.y, hi[p + 2], lo[p + 2]);
                split_pair(f1.z, f1.w, hi[p + 3], lo[p + 3]);
            }
            #pragma unroll
            for (int j = 0; j < 2; j++)
                #pragma unroll
                for (int q = 0; q < 4; q++) {
                    uint4 blk = make_uint4(hi[8 * j + q], hi[8 * j + q + 4],
                                           lo[8 * j + q], lo[8 * j + q + 4]);
                    *(uint4*)(smc + E_SA + addr64(m, 2 * h + j, q)) = blk;
                }
        }
        __syncthreads();

        // ---- GEMM1: acc1 += ea @ W1 (K=64, 3 split terms) ----
        #pragma unroll
        for (int ks = 0; ks < 4; ks++) {
            uint4 A0 = *(const uint4*)(smc + E_SA + addr64(mrow0, ks, qt));
            uint4 A1 = *(const uint4*)(smc + E_SA + addr64(mrow0 + 8, ks, qt));
            uint32_t ah[4] = {A0.x, A1.x, A0.y, A1.y};
            uint32_t al[4] = {A0.z, A1.z, A0.w, A1.w};
            #pragma unroll
            for (int nt = 0; nt < 16; nt++) {
                uint4 B = *(const uint4*)(smc + E_SW1 + addr64(8 * nt + g, ks, qt));
                uint32_t bh[2] = {B.x, B.y}, bl[2] = {B.z, B.w};
                mma_bf16(acc1[nt], ah, bh);
                mma_bf16(acc1[nt], ah, bl);
                mma_bf16(acc1[nt], al, bh);
            }
        }
        __syncthreads();   // all sA reads done -> next tile may rebuild A

        // ---- pack H fragments (relu fused); acc1 dies here ----
        uint32_t hA[8][4], lA[8][4];
        #pragma unroll
        for (int ks = 0; ks < 8; ks++) {
            float v00 = fmaxf(acc1[2 * ks][0], 0.f);
            float v01 = fmaxf(acc1[2 * ks][1], 0.f);
            float v02 = fmaxf(acc1[2 * ks][2], 0.f);
            float v03 = fmaxf(acc1[2 * ks][3], 0.f);
            float v10 = fmaxf(acc1[2 * ks + 1][0], 0.f);
            float v11 = fmaxf(acc1[2 * ks + 1][1], 0.f);
            float v12 = fmaxf(acc1[2 * ks + 1][2], 0.f);
            float v13 = fmaxf(acc1[2 * ks + 1][3], 0.f);
            split_pair(v00, v01, hA[ks][0], lA[ks][0]);
            split_pair(v02, v03, hA[ks][1], lA[ks][1]);
            split_pair(v10, v11, hA[ks][2], lA[ks][2]);
            split_pair(v12, v13, hA[ks][3], lA[ks][3]);
        }

        // ---- GEMM2: acc2 = H @ W2 (K=128) from packed registers ----
        float acc2[8][4];
        #pragma unroll
        for (int nt = 0; nt < 8; nt++)
            #pragma unroll
            for (int j = 0; j < 4; j++) acc2[nt][j] = 0.f;

        #pragma unroll
        for (int ks = 0; ks < 8; ks++) {
            #pragma unroll
            for (int nt = 0; nt < 8; nt++) {
                uint4 B = *(const uint4*)(smc + E_SW2 + addr128k(8 * nt + g, ks, qt));
                uint32_t bh[2] = {B.x, B.y}, bl[2] = {B.z, B.w};
                mma_bf16(acc2[nt], hA[ks], bh);
                mma_bf16(acc2[nt], hA[ks], bl);
                mma_bf16(acc2[nt], lA[ks], bh);
            }
        }

        // ---- epilogue: red.add agg[row]; dst = ea + (D2 + b2) ----
        #pragma unroll
        for (int nt = 0; nt < 8; nt++) {
            int col = 8 * nt + 2 * qt;
            float vx0 = acc2[nt][0] + sb2[col];
            float vy0 = acc2[nt][1] + sb2[col + 1];
            float vx1 = acc2[nt][2] + sb2[col];
            float vy1 = acc2[nt][3] + sb2[col + 1];
            float* ap0 = agg + (size_t)r0 * DD + col;
            float* ap1 = agg + (size_t)r1 * DD + col;
            asm volatile("red.global.add.v2.f32 [%0], {%1, %2};"
                         :: "l"(ap0), "f"(vx0), "f"(vy0) : "memory");
            asm volatile("red.global.add.v2.f32 [%0], {%1, %2};"
                         :: "l"(ap1), "f"(vx1), "f"(vy1) : "memory");
            size_t o0 = (size_t)(i0 + mrow0) * DD + col;
            size_t o1 = (size_t)(i0 + mrow0 + 8) * DD + col;
            float2 e0 = *(const float2*)(ea + o0);
            float2 e1 = *(const float2*)(ea + o1);
            *(float2*)(dst + o0) = make_float2(e0.x + vx0, e0.y + vy0);
            *(float2*)(dst + o1) = make_float2(e1.x + vx1, e1.y + vy1);
        }
    }
}

// ---------------- node / px kernels (round-8, known good) ------------------
#define OFF_AH   0
#define OFF_AL   34816
#define OFF_W1H  69632
#define OFF_W1L  104448
#define OFF_W2H  139264
#define OFF_W2L  156672
#define OFF_B1   174080
#define OFF_B2   174592
#define SMEMSZ   175360

__global__ void __launch_bounds__(256, 1)
px_k(const float* __restrict__ x, const float* __restrict__ Wc,
     const float* __restrict__ be1, float* __restrict__ Px)
{
    extern __shared__ char smc[];
    uint16_t* sAh = (uint16_t*)(smc + OFF_AH);
    uint16_t* sAl = (uint16_t*)(smc + OFF_AL);
    uint16_t* sWh = (uint16_t*)(smc + OFF_W1H);
    uint16_t* sWl = (uint16_t*)(smc + OFF_W1L);
    float*    sb1 = (float*)(smc + OFF_B1);

    const int tid = threadIdx.x;
    const int lane = tid & 31, w = tid >> 5;
    const int g = lane >> 2, qt = lane & 3;
    const int wm = w >> 1, wn = w & 1;

    {
        int n = tid & 127, k0 = (tid >> 7) * 32;
        for (int k = k0; k < k0 + 32; k += 2) {
            uint32_t hi, lo;
            split_pair(Wc[k * 128 + n], Wc[(k + 1) * 128 + n], hi, lo);
            *(uint32_t*)&sWh[n * KP + k] = hi;
            *(uint32_t*)&sWl[n * KP + k] = lo;
        }
    }
    if (tid < 128) sb1[tid] = be1[tid];
    __syncthreads();

    for (int tile = blockIdx.x; tile < NT; tile += gridDim.x) {
        const int i0 = tile * 128;
        {
            const int m = tid & 127, ch = (tid >> 7) * 32;
            const int gi = i0 + m;
            const bool valid = gi < NN;
            const float* src = x + (size_t)(valid ? gi : 0) * DD + ch;
            #pragma unroll
            for (int c = 0; c < 32; c += 8) {
                float4 f0, f1;
                if (valid) { f0 = *(const float4*)(src + c); f1 = *(const float4*)(src + c + 4); }
                else { f0 = make_float4(0,0,0,0); f1 = f0; }
                uint32_t hw[4], lw[4];
                split_pair(f0.x, f0.y, hw[0], lw[0]);
                split_pair(f0.z, f0.w, hw[1], lw[1]);
                split_pair(f1.x, f1.y, hw[2], lw[2]);
                split_pair(f1.z, f1.w, hw[3], lw[3]);
                int e = m * KP + ch + c;
                *(uint4*)&sAh[e] = *(uint4*)hw;
                *(uint4*)&sAl[e] = *(uint4*)lw;
            }
        }
        __syncthreads();

        float acc[2][8][4];
        #pragma unroll
        for (int mt = 0; mt < 2; mt++)
            #pragma unroll
            for (int nt = 0; nt < 8; nt++)
                #pragma unroll
                for (int j = 0; j < 4; j++) acc[mt][nt][j] = 0.f;

        #pragma unroll
        for (int ks = 0; ks < 4; ks++) {
            const int kb = ks * 16 + 2 * qt;
            uint32_t ah[2][4], al[2][4];
            #pragma unroll
            for (int mt = 0; mt < 2; mt++) {
                int e = (wm * 32 + mt * 16 + g) * KP + kb;
                ah[mt][0] = *(const uint32_t*)&sAh[e];
                ah[mt][1] = *(const uint32_t*)&sAh[e + 8 * KP];
                ah[mt][2] = *(const uint32_t*)&sAh[e + 8];
                ah[mt][3] = *(const uint32_t*)&sAh[e + 8 * KP + 8];
                al[mt][0] = *(const uint32_t*)&sAl[e];
                al[mt][1] = *(const uint32_t*)&sAl[e + 8 * KP];
                al[mt][2] = *(const uint32_t*)&sAl[e + 8];
                al[mt][3] = *(const uint32_t*)&sAl[e + 8 * KP + 8];
            }
            #pragma unroll
            for (int nt = 0; nt < 8; nt++) {
                int e = (wn * 64 + nt * 8 + g) * KP + kb;
                uint32_t bh[2], bl[2];
                bh[0] = *(const uint32_t*)&sWh[e];
                bh[1] = *(const uint32_t*)&sWh[e + 8];
                bl[0] = *(const uint32_t*)&sWl[e];
                bl[1] = *(const uint32_t*)&sWl[e + 8];
                mma_bf16(acc[0][nt], ah[0], bh);
                mma_bf16(acc[1][nt], ah[1], bh);
                mma_bf16(acc[0][nt], ah[0], bl);
                mma_bf16(acc[1][nt], ah[1], bl);
                mma_bf16(acc[0][nt], al[0], bh);
                mma_bf16(acc[1][nt], al[1], bh);
            }
        }

        #pragma unroll
        for (int mt = 0; mt < 2; mt++)
            #pragma unroll
            for (int nt = 0; nt < 8; nt++) {
                int rl = wm * 32 + mt * 16 + g;
                int col = wn * 64 + nt * 8 + 2 * qt;
                #pragma unroll
                for (int rh = 0; rh < 2; rh++) {
                    int gi = i0 + rl + rh * 8;
                    if (gi >= NN) continue;
                    float2 v = make_float2(acc[mt][nt][rh * 2] + sb1[col],
                                           acc[mt][nt][rh * 2 + 1] + sb1[col + 1]);
                    *(float2*)&Px[(size_t)gi * 128 + col] = v;
                }
            }
        __syncthreads();
    }
}

__global__ void __launch_bounds__(256, 1)
node_mma(const float* __restrict__ x_src, const float* __restrict__ a_src,
         const float* __restrict__ W1, const float* __restrict__ b1,
         const float* __restrict__ W2, const float* __restrict__ b2,
         float* __restrict__ dst, const float* __restrict__ inv, int count)
{
    extern __shared__ char smc[];
    uint16_t* sAh  = (uint16_t*)(smc + OFF_AH);
    uint16_t* sAl  = (uint16_t*)(smc + OFF_AL);
    uint16_t* sW1h = (uint16_t*)(smc + OFF_W1H);
    uint16_t* sW1l = (uint16_t*)(smc + OFF_W1L);
    uint16_t* sW2h = (uint16_t*)(smc + OFF_W2H);
    uint16_t* sW2l = (uint16_t*)(smc + OFF_W2L);
    float*    sb1  = (float*)(smc + OFF_B1);
    float*    sb2  = (float*)(smc + OFF_B2);

    const int tid = threadIdx.x;
    const int lane = tid & 31, w = tid >> 5;
    const int g = lane >> 2, qt = lane & 3;
    const int wm = w >> 1, wn = w & 1;

    {
        int n = tid & 127, k0 = (tid >> 7) * 64;
        for (int k = k0; k < k0 + 64; k += 2) {
            uint32_t hi, lo;
            split_pair(W1[k * 128 + n], W1[(k + 1) * 128 + n], hi, lo);
            *(uint32_t*)&sW1h[n * KP + k] = hi;
            *(uint32_t*)&sW1l[n * KP + k] = lo;
        }
    }
    {
        int n = tid & 63, k0 = (tid >> 6) * 32;
        for (int k = k0; k < k0 + 32; k += 2) {
            uint32_t hi, lo;
            split_pair(W2[k * 64 + n], W2[(k + 1) * 64 + n], hi, lo);
            *(uint32_t*)&sW2h[n * KP + k] = hi;
            *(uint32_t*)&sW2l[n * KP + k] = lo;
        }
    }
    if (tid < 128) sb1[tid] = b1[tid];
    if (tid < 64)  sb2[tid] = b2[tid];
    __syncthreads();

    for (int tile = blockIdx.x; tile < NT; tile += gridDim.x) {
        const int i0 = tile * 128;
        {
            const int m = tid & 127, half = tid >> 7;
            const int gi = i0 + m;
            const bool valid = gi < count;
            const float* src;
            float scale = 1.0f;
            bool doscale = false;
            if (half == 0) {
                src = x_src + (size_t)(valid ? gi : 0) * DD;
            } else {
                src = a_src + (size_t)(valid ? gi : 0) * DD;
                scale = valid ? inv[gi] : 0.0f;
                doscale = true;
            }
            #pragma unroll
            for (int c = 0; c < 64; c += 8) {
                float4 f0 = *(const float4*)(src + c);
                float4 f1 = *(const float4*)(src + c + 4);
                if (doscale) {
                    f0.x *= scale; f0.y *= scale; f0.z *= scale; f0.w *= scale;
                    f1.x *= scale; f1.y *= scale; f1.z *= scale; f1.w *= scale;
                }
                uint32_t hw[4], lw[4];
                split_pair(f0.x, f0.y, hw[0], lw[0]);
                split_pair(f0.z, f0.w, hw[1], lw[1]);
                split_pair(f1.x, f1.y, hw[2], lw[2]);
                split_pair(f1.z, f1.w, hw[3], lw[3]);
                int e = m * KP + half * 64 + c;
                *(uint4*)&sAh[e] = *(uint4*)hw;
                *(uint4*)&sAl[e] = *(uint4*)lw;
            }
        }
        __syncthreads();

        float acc[2][8][4];
        #pragma unroll
        for (int mt = 0; mt < 2; mt++)
            #pragma unroll
            for (int nt = 0; nt < 8; nt++)
                #pragma unroll
                for (int j = 0; j < 4; j++) acc[mt][nt][j] = 0.f;

        #pragma unroll
        for (int ks = 0; ks < 8; ks++) {
            const int kb = ks * 16 + 2 * qt;
            uint32_t ah[2][4], al[2][4];
            #pragma unroll
            for (int mt = 0; mt < 2; mt++) {
                int e = (wm * 32 + mt * 16 + g) * KP + kb;
                ah[mt][0] = *(const uint32_t*)&sAh[e];
                ah[mt][1] = *(const uint32_t*)&sAh[e + 8 * KP];
                ah[mt][2] = *(const uint32_t*)&sAh[e + 8];
                ah[mt][3] = *(const uint32_t*)&sAh[e + 8 * KP + 8];
                al[mt][0] = *(const uint32_t*)&sAl[e];
                al[mt][1] = *(const uint32_t*)&sAl[e + 8 * KP];
                al[mt][2] = *(const uint32_t*)&sAl[e + 8];
                al[mt][3] = *(const uint32_t*)&sAl[e + 8 * KP + 8];
            }
            #pragma unroll
            for (int nt = 0; nt < 8; nt++) {
                int e = (wn * 64 + nt * 8 + g) * KP + kb;
                uint32_t bh[2], bl[2];
                bh[0] = *(const uint32_t*)&sW1h[e];
                bh[1] = *(const uint32_t*)&sW1h[e + 8];
                bl[0] = *(const uint32_t*)&sW1l[e];
                bl[1] = *(const uint32_t*)&sW1l[e + 8];
                mma_bf16(acc[0][nt], ah[0], bh);
                mma_bf16(acc[1][nt], ah[1], bh);
                mma_bf16(acc[0][nt], ah[0], bl);
                mma_bf16(acc[1][nt], ah[1], bl);
                mma_bf16(acc[0][nt], al[0], bh);
                mma_bf16(acc[1][nt], al[1], bh);
            }
        }
        __syncthreads();

        #pragma unroll
        for (int mt = 0; mt < 2; mt++)
            #pragma unroll
            for (int nt = 0; nt < 8; nt++) {
                int row = wm * 32 + mt * 16 + g;
                int col = wn * 64 + nt * 8 + 2 * qt;
                float v0 = fmaxf(acc[mt][nt][0] + sb1[col], 0.f);
                float v1 = fmaxf(acc[mt][nt][1] + sb1[col + 1], 0.f);
                float v2 = fmaxf(acc[mt][nt][2] + sb1[col], 0.f);
                float v3 = fmaxf(acc[mt][nt][3] + sb1[col + 1], 0.f);
                uint32_t hi, lo;
                split_pair(v0, v1, hi, lo);
                *(uint32_t*)&sAh[row * KP + col] = hi;
                *(uint32_t*)&sAl[row * KP + col] = lo;
                split_pair(v2, v3, hi, lo);
                *(uint32_t*)&sAh[(row + 8) * KP + col] = hi;
                *(uint32_t*)&sAl[(row + 8) * KP + col] = lo;
            }
        __syncthreads();

        float acc2[2][4][4];
        #pragma unroll
        for (int mt = 0; mt < 2; mt++)
            #pragma unroll
            for (int nt = 0; nt < 4; nt++)
                #pragma unroll
                for (int j = 0; j < 4; j++) acc2[mt][nt][j] = 0.f;

        #pragma unroll
        for (int ks = 0; ks < 8; ks++) {
            const int kb = ks * 16 + 2 * qt;
            uint32_t ah[2][4], al[2][4];
            #pragma unroll
            for (int mt = 0; mt < 2; mt++) {
                int e = (wm * 32 + mt * 16 + g) * KP + kb;
                ah[mt][0] = *(const uint32_t*)&sAh[e];
                ah[mt][1] = *(const uint32_t*)&sAh[e + 8 * KP];
                ah[mt][2] = *(const uint32_t*)&sAh[e + 8];
                ah[mt][3] = *(const uint32_t*)&sAh[e + 8 * KP + 8];
                al[mt][0] = *(const uint32_t*)&sAl[e];
                al[mt][1] = *(const uint32_t*)&sAl[e + 8 * KP];
                al[mt][2] = *(const uint32_t*)&sAl[e + 8];
                al[mt][3] = *(const uint32_t*)&sAl[e + 8 * KP + 8];
            }
            #pragma unroll
            for (int nt = 0; nt < 4; nt++) {
                int e = (wn * 32 + nt * 8 + g) * KP + kb;
                uint32_t bh[2], bl[2];
                bh[0] = *(const uint32_t*)&sW2h[e];
                bh[1] = *(const uint32_t*)&sW2h[e + 8];
                bl[0] = *(const uint32_t*)&sW2l[e];
                bl[1] = *(const uint32_t*)&sW2l[e + 8];
                mma_bf16(acc2[0][nt], ah[0], bh);
                mma_bf16(acc2[1][nt], ah[1], bh);
                mma_bf16(acc2[0][nt], ah[0], bl);
                mma_bf16(acc2[1][nt], ah[1], bl);
                mma_bf16(acc2[0][nt], al[0], bh);
                mma_bf16(acc2[1][nt], al[1], bh);
            }
        }

        #pragma unroll
        for (int mt = 0; mt < 2; mt++)
            #pragma unroll
            for (int nt = 0; nt < 4; nt++) {
                int rl = wm * 32 + mt * 16 + g;
                int col = wn * 32 + nt * 8 + 2 * qt;
                #pragma unroll
                for (int rh = 0; rh < 2; rh++) {
                    int row = rl + rh * 8;
                    int gi = i0 + row;
                    if (gi >= count) continue;
                    float vx = acc2[mt][nt][rh * 2 + 0] + sb2[col];
                    float vy = acc2[mt][nt][rh * 2 + 1] + sb2[col + 1];
                    float2 rv = *(const float2*)(x_src + (size_t)gi * DD + col);
                    *(float2*)(dst + (size_t)gi * DD + col) =
                        make_float2(rv.x + vx, rv.y + vy);
                }
            }
        __syncthreads();
    }
}

extern "C" void kernel_launch(void* const* d_in, const int* in_sizes, int n_in,
                              void* d_out, int out_size)
{
    const float* x   = (const float*)d_in[0];
    const float* ea  = (const float*)d_in[1];
    const float* We1 = (const float*)d_in[2];
    const float* be1 = (const float*)d_in[3];
    const float* We2 = (const float*)d_in[4];
    const float* be2 = (const float*)d_in[5];
    const float* Wn1 = (const float*)d_in[6];
    const float* bn1 = (const float*)d_in[7];
    const float* Wn2 = (const float*)d_in[8];
    const float* bn2 = (const float*)d_in[9];
    const void*  eidx = d_in[10];

    float* out_x  = (float*)d_out;
    float* out_ea = (float*)d_out + (size_t)NN * DD;

    float *agg, *inv, *Wc, *Px;
    int* cnt;
    cudaGetSymbolAddress((void**)&agg, g_agg);
    cudaGetSymbolAddress((void**)&inv, g_inv);
    cudaGetSymbolAddress((void**)&cnt, g_cnt);
    cudaGetSymbolAddress((void**)&Wc,  g_Wc);
    cudaGetSymbolAddress((void**)&Px,  g_Px);

    cudaFuncSetAttribute(edge_mma, cudaFuncAttributeMaxDynamicSharedMemorySize, E_SMEM);
    cudaFuncSetAttribute(node_mma, cudaFuncAttributeMaxDynamicSharedMemorySize, SMEMSZ);
    cudaFuncSetAttribute(px_k,     cudaFuncAttributeMaxDynamicSharedMemorySize, SMEMSZ);

    int smcount = 148;
    cudaDeviceGetAttribute(&smcount, cudaDevAttrMultiProcessorCount, 0);
    int ge = 2 * smcount < ET ? 2 * smcount : ET;
    int gn = smcount < NT ? smcount : NT;

    // Edge kernel is my 4th launch (global #6 with harness prelaunches; -s 5 window).
    prolog_k<<<(NN * DD / 4 + 255) / 256, 256>>>(eidx, agg, cnt);        // 0
    combine_w_k<<<(128 * 128 + 255) / 256, 256>>>(We1, Wc);              // 1
    px_k<<<gn, 256, SMEMSZ>>>(x, Wc, be1, Px);                           // 2
    edge_mma<<<ge, 256, E_SMEM>>>(ea, eidx, Px, Wc, We2, be2,            // 3 <- profiled
                                  out_ea, agg, ET);
    count_k<<<(EE + 255) / 256, 256>>>(eidx, cnt);                       // 4
    inv_k<<<(NN + 255) / 256, 256>>>(cnt, inv);                          // 5
    node_mma<<<gn, 256, SMEMSZ>>>(x, agg, Wn1, bn1, Wn2, bn2,            // 6
                                  out_x, inv, NN);

    // iteration 2
    zero_f4<<<(NN * DD / 4 + 255) / 256, 256>>>(agg, NN * DD / 4);
    px_k<<<gn, 256, SMEMSZ>>>(out_x, Wc, be1, Px);
    edge_mma<<<ge, 256, E_SMEM>>>(out_ea, eidx, Px, Wc, We2, be2,
                                  out_ea, agg, ET);
    node_mma<<<gn, 256, SMEMSZ>>>(out_x, agg, Wn1, bn1, Wn2, bn2,
                                  out_x, inv, NN);
}

// round 10
// speedup vs baseline: 1.1384x; 1.0752x over previous
#include <cuda_runtime.h>
#include <cuda_bf16.h>
#include <cstdint>

#define NN 50000
#define EE 800000
#define DD 64
#define ET 6250                 // EE / 128
#define NT 391                  // ceil(NN / 128)
#define KP 136                  // node-kernel padded K stride (bf16)

// ---------------- device-global scratch (no allocations allowed) ----------
__device__ float g_agg[NN * DD];
__device__ float g_inv[NN];
__device__ int   g_cnt[NN];
__device__ float g_Wc[128 * 128];
__device__ float g_Px[NN * 128];   // per-node x @ Wc[0:64] + be1
__device__ int   g_is64;

__device__ __forceinline__ int load_row(const void* eidx, int i) {
    if (g_is64) return (int)((const long long*)eidx)[i];
    return ((const int*)eidx)[i];
}

__global__ void prolog_k(const void* eidx, float* agg, int* cnt) {
    int i = blockIdx.x * blockDim.x + threadIdx.x;
    if (i < NN * DD / 4) ((float4*)agg)[i] = make_float4(0.f, 0.f, 0.f, 0.f);
    if (i < NN) cnt[i] = 0;
    if (i == 0) {
        const long long* p = (const long long*)eidx;
        int ok = 1;
        for (int j = 0; j < 64; j++) {
            long long v = p[j];
            if (v < 0 || v >= NN) { ok = 0; break; }
        }
        g_is64 = ok;
    }
}

__global__ void combine_w_k(const float* __restrict__ We1, float* __restrict__ Wc) {
    int i = blockIdx.x * blockDim.x + threadIdx.x;
    if (i < 128 * 128) {
        int k = i >> 7, n = i & 127;
        float v = We1[(k + 64) * 128 + n];
        if (k < 64) v += We1[k * 128 + n];
        Wc[i] = v;
    }
}

__global__ void zero_f4(float* p, int n4) {
    int i = blockIdx.x * blockDim.x + threadIdx.x;
    if (i < n4) ((float4*)p)[i] = make_float4(0.f, 0.f, 0.f, 0.f);
}
__global__ void count_k(const void* eidx, int* cnt) {
    int i = blockIdx.x * blockDim.x + threadIdx.x;
    if (i < EE) atomicAdd(&cnt[load_row(eidx, i)], 1);
}
__global__ void inv_k(const int* __restrict__ cnt, float* __restrict__ inv) {
    int i = blockIdx.x * blockDim.x + threadIdx.x;
    if (i < NN) inv[i] = 1.0f / fmaxf((float)cnt[i], 1.0f);
}

// ---------------- helpers ---------------------------------------------------
// Fast bf16 split-2: 6 instructions via packed cvt.rn.bf16x2.f32 (sm_80+ PTX).
// hi = packed bf16x2 of (f0,f1); lo = packed bf16x2 of exact residuals.
__device__ __forceinline__ void split_pair(float f0, float f1, uint32_t& hi, uint32_t& lo) {
    asm("cvt.rn.bf16x2.f32 %0, %1, %2;" : "=r"(hi) : "f"(f1), "f"(f0));
    float h0 = __uint_as_float(hi << 16);
    float h1 = __uint_as_float(hi & 0xFFFF0000u);
    float r0 = f0 - h0;
    float r1 = f1 - h1;
    asm("cvt.rn.bf16x2.f32 %0, %1, %2;" : "=r"(lo) : "f"(r1), "f"(r0));
}

// m16n8k16 row.col bf16 -> f32 accumulate (baseline PTX, sm_80+)
__device__ __forceinline__ void mma_bf16(float* d, const uint32_t* a, const uint32_t* b) {
    asm volatile(
        "mma.sync.aligned.m16n8k16.row.col.f32.bf16.bf16.f32 "
        "{%0,%1,%2,%3}, {%4,%5,%6,%7}, {%8,%9}, {%0,%1,%2,%3};"
        : "+f"(d[0]), "+f"(d[1]), "+f"(d[2]), "+f"(d[3])
        : "r"(a[0]), "r"(a[1]), "r"(a[2]), "r"(a[3]), "r"(b[0]), "r"(b[1]));
}

// ================= EDGE KERNEL: fragment-blocked smem, LDS.128 =============
// 16B block per (row, ks, qt): {hi(k,k+1), hi(k+8,k+9), lo(k,k+1), lo(k+8,k+9)},
// k = 16*ks + 2*qt. XOR swizzle chunk = (ks ^ (row&3))*4 + qt -> conflict-free
// LDS.128 phases.
#define E_SA   0                  // A:  128 rows x 256B (K=64)
#define E_SW1  32768              // W1: 128 rows x 256B (K=64)
#define E_SW2  65536              // W2:  64 rows x 512B (K=128)
#define E_B2   98304              // 64 f32
#define E_SMEM 98560

__device__ __forceinline__ uint32_t addr64(int row, int ks, int qt) {   // 256B stride
    return ((uint32_t)row << 8) + ((uint32_t)(((ks ^ (row & 3)) << 2) + qt) << 4);
}
__device__ __forceinline__ uint32_t addr128k(int row, int ks, int qt) { // 512B stride
    return ((uint32_t)row << 9) + ((uint32_t)(((ks ^ (row & 3)) << 2) + qt) << 4);
}

__global__ void __launch_bounds__(256, 2)
edge_mma(const float* __restrict__ ea, const void* __restrict__ eidx,
         const float* __restrict__ Px,
         const float* __restrict__ Wc, const float* __restrict__ W2,
         const float* __restrict__ b2,
         float* __restrict__ dst, float* __restrict__ agg, int ntiles)
{
    extern __shared__ char smc[];
    float* sb2 = (float*)(smc + E_B2);

    const int tid = threadIdx.x;
    const int lane = tid & 31, w = tid >> 5;
    const int g = lane >> 2, qt = lane & 3;

    // ---- stage W1 = Wc rows 64:127 (K=64) in fragment blocks ----
    {
        const int n = tid & 127, h = tid >> 7;
        uint32_t hi[16], lo[16];
        #pragma unroll
        for (int p = 0; p < 16; p++) {
            int k = 32 * h + 2 * p;
            split_pair(Wc[(64 + k) * 128 + n], Wc[(64 + k + 1) * 128 + n], hi[p], lo[p]);
        }
        #pragma unroll
        for (int j = 0; j < 2; j++)
            #pragma unroll
            for (int q = 0; q < 4; q++) {
                uint4 blk = make_uint4(hi[8 * j + q], hi[8 * j + q + 4],
                                       lo[8 * j + q], lo[8 * j + q + 4]);
                *(uint4*)(smc + E_SW1 + addr64(n, 2 * h + j, q)) = blk;
            }
    }
    // ---- stage W2 (64n x K=128) in fragment blocks ----
    {
        const int n = tid & 63, kq = tid >> 6;
        uint32_t hi[16], lo[16];
        #pragma unroll
        for (int p = 0; p < 16; p++) {
            int k = 32 * kq + 2 * p;
            split_pair(W2[k * 64 + n], W2[(k + 1) * 64 + n], hi[p], lo[p]);
        }
        #pragma unroll
        for (int j = 0; j < 2; j++)
            #pragma unroll
            for (int q = 0; q < 4; q++) {
                uint4 blk = make_uint4(hi[8 * j + q], hi[8 * j + q + 4],
                                       lo[8 * j + q], lo[8 * j + q + 4]);
                *(uint4*)(smc + E_SW2 + addr128k(n, 2 * kq + j, q)) = blk;
            }
    }
    if (tid < 64) sb2[tid] = b2[tid];
    __syncthreads();

    for (int tile = blockIdx.x; tile < ntiles; tile += gridDim.x) {
        const int i0 = tile * 128;
        const int mrow0 = 16 * w + g;

        const int r0 = load_row(eidx, i0 + mrow0);
        const int r1 = load_row(eidx, i0 + mrow0 + 8);

        // ---- init acc1 from Px gather (be1 folded into Px) ----
        float acc1[16][4];
        #pragma unroll
        for (int nt = 0; nt < 16; nt++) {
            int col = 8 * nt + 2 * qt;
            float2 v0 = *(const float2*)&Px[(size_t)r0 * 128 + col];
            float2 v1 = *(const float2*)&Px[(size_t)r1 * 128 + col];
            acc1[nt][0] = v0.x; acc1[nt][1] = v0.y;
            acc1[nt][2] = v1.x; acc1[nt][3] = v1.y;
        }

        // ---- build A tile (K=64) in fragment blocks ----
        {
            const int m = tid & 127, h = tid >> 7;
            const float* src = ea + (size_t)(i0 + m) * DD + 32 * h;
            uint32_t hi[16], lo[16];
            #pragma unroll
            for (int c = 0; c < 32; c += 8) {
                float4 f0 = *(const float4*)(src + c);
                float4 f1 = *(const float4*)(src + c + 4);
                int p = c >> 1;
                split_pair(f0.x, f0.y, hi[p],     lo[p]);
                split_pair(f0.z, f0.w, hi[p + 1], lo[p + 1]);
                split_pair(f1.x, f1.y, hi[p + 2], lo[p + 2]);
                split_pair(f1.z, f1.w, hi[p + 3], lo[p + 3]);
            }
            #pragma unroll
            for (int j = 0; j < 2; j++)
                #pragma unroll
                for (int q = 0; q < 4; q++) {
                    uint4 blk = make_uint4(hi[8 * j + q], hi[8 * j + q + 4],
                                           lo[8 * j + q], lo[8 * j + q + 4]);
                    *(uint4*)(smc + E_SA + addr64(m, 2 * h + j, q)) = blk;
                }
        }
        __syncthreads();

        // ---- GEMM1: acc1 += ea @ W1 (K=64, 3 split terms) ----
        #pragma unroll
        for (int ks = 0; ks < 4; ks++) {
            uint4 A0 = *(const uint4*)(smc + E_SA + addr64(mrow0, ks, qt));
            uint4 A1 = *(const uint4*)(smc + E_SA + addr64(mrow0 + 8, ks, qt));
            uint32_t ah[4] = {A0.x, A1.x, A0.y, A1.y};
            uint32_t al[4] = {A0.z, A1.z, A0.w, A1.w};
            #pragma unroll
            for (int nt = 0; nt < 16; nt++) {
                uint4 B = *(const uint4*)(smc + E_SW1 + addr64(8 * nt + g, ks, qt));
                uint32_t bh[2] = {B.x, B.y}, bl[2] = {B.z, B.w};
                mma_bf16(acc1[nt], ah, bh);
                mma_bf16(acc1[nt], ah, bl);
                mma_bf16(acc1[nt], al, bh);
            }
        }
        __syncthreads();

        // ---- pack H fragments (relu fused); acc1 dies here ----
        uint32_t hA[8][4], lA[8][4];
        #pragma unroll
        for (int ks = 0; ks < 8; ks++) {
            float v00 = fmaxf(acc1[2 * ks][0], 0.f);
            float v01 = fmaxf(acc1[2 * ks][1], 0.f);
            float v02 = fmaxf(acc1[2 * ks][2], 0.f);
            float v03 = fmaxf(acc1[2 * ks][3], 0.f);
            float v10 = fmaxf(acc1[2 * ks + 1][0], 0.f);
            float v11 = fmaxf(acc1[2 * ks + 1][1], 0.f);
            float v12 = fmaxf(acc1[2 * ks + 1][2], 0.f);
            float v13 = fmaxf(acc1[2 * ks + 1][3], 0.f);
            split_pair(v00, v01, hA[ks][0], lA[ks][0]);
            split_pair(v02, v03, hA[ks][1], lA[ks][1]);
            split_pair(v10, v11, hA[ks][2], lA[ks][2]);
            split_pair(v12, v13, hA[ks][3], lA[ks][3]);
        }

        // ---- GEMM2: acc2 = H @ W2 (K=128) from packed registers ----
        float acc2[8][4];
        #pragma unroll
        for (int nt = 0; nt < 8; nt++)
            #pragma unroll
            for (int j = 0; j < 4; j++) acc2[nt][j] = 0.f;

        #pragma unroll
        for (int ks = 0; ks < 8; ks++) {
            #pragma unroll
            for (int nt = 0; nt < 8; nt++) {
                uint4 B = *(const uint4*)(smc + E_SW2 + addr128k(8 * nt + g, ks, qt));
                uint32_t bh[2] = {B.x, B.y}, bl[2] = {B.z, B.w};
                mma_bf16(acc2[nt], hA[ks], bh);
                mma_bf16(acc2[nt], hA[ks], bl);
                mma_bf16(acc2[nt], lA[ks], bh);
            }
        }

        // ---- epilogue: red.add agg[row]; dst = ea + (D2 + b2) ----
        #pragma unroll
        for (int nt = 0; nt < 8; nt++) {
            int col = 8 * nt + 2 * qt;
            float vx0 = acc2[nt][0] + sb2[col];
            float vy0 = acc2[nt][1] + sb2[col + 1];
            float vx1 = acc2[nt][2] + sb2[col];
            float vy1 = acc2[nt][3] + sb2[col + 1];
            float* ap0 = agg + (size_t)r0 * DD + col;
            float* ap1 = agg + (size_t)r1 * DD + col;
            asm volatile("red.global.add.v2.f32 [%0], {%1, %2};"
                         :: "l"(ap0), "f"(vx0), "f"(vy0) : "memory");
            asm volatile("red.global.add.v2.f32 [%0], {%1, %2};"
                         :: "l"(ap1), "f"(vx1), "f"(vy1) : "memory");
            size_t o0 = (size_t)(i0 + mrow0) * DD + col;
            size_t o1 = (size_t)(i0 + mrow0 + 8) * DD + col;
            float2 e0 = *(const float2*)(ea + o0);
            float2 e1 = *(const float2*)(ea + o1);
            *(float2*)(dst + o0) = make_float2(e0.x + vx0, e0.y + vy0);
            *(float2*)(dst + o1) = make_float2(e1.x + vx1, e1.y + vy1);
        }
    }
}

// ---------------- node / px kernels (round-9, known good) ------------------
#define OFF_AH   0
#define OFF_AL   34816
#define OFF_W1H  69632
#define OFF_W1L  104448
#define OFF_W2H  139264
#define OFF_W2L  156672
#define OFF_B1   174080
#define OFF_B2   174592
#define SMEMSZ   175360

__global__ void __launch_bounds__(256, 1)
px_k(const float* __restrict__ x, const float* __restrict__ Wc,
     const float* __restrict__ be1, float* __restrict__ Px)
{
    extern __shared__ char smc[];
    uint16_t* sAh = (uint16_t*)(smc + OFF_AH);
    uint16_t* sAl = (uint16_t*)(smc + OFF_AL);
    uint16_t* sWh = (uint16_t*)(smc + OFF_W1H);
    uint16_t* sWl = (uint16_t*)(smc + OFF_W1L);
    float*    sb1 = (float*)(smc + OFF_B1);

    const int tid = threadIdx.x;
    const int lane = tid & 31, w = tid >> 5;
    const int g = lane >> 2, qt = lane & 3;
    const int wm = w >> 1, wn = w & 1;

    {
        int n = tid & 127, k0 = (tid >> 7) * 32;
        for (int k = k0; k < k0 + 32; k += 2) {
            uint32_t hi, lo;
            split_pair(Wc[k * 128 + n], Wc[(k + 1) * 128 + n], hi, lo);
            *(uint32_t*)&sWh[n * KP + k] = hi;
            *(uint32_t*)&sWl[n * KP + k] = lo;
        }
    }
    if (tid < 128) sb1[tid] = be1[tid];
    __syncthreads();

    for (int tile = blockIdx.x; tile < NT; tile += gridDim.x) {
        const int i0 = tile * 128;
        {
            const int m = tid & 127, ch = (tid >> 7) * 32;
            const int gi = i0 + m;
            const bool valid = gi < NN;
            const float* src = x + (size_t)(valid ? gi : 0) * DD + ch;
            #pragma unroll
            for (int c = 0; c < 32; c += 8) {
                float4 f0, f1;
                if (valid) { f0 = *(const float4*)(src + c); f1 = *(const float4*)(src + c + 4); }
                else { f0 = make_float4(0,0,0,0); f1 = f0; }
                uint32_t hw[4], lw[4];
                split_pair(f0.x, f0.y, hw[0], lw[0]);
                split_pair(f0.z, f0.w, hw[1], lw[1]);
                split_pair(f1.x, f1.y, hw[2], lw[2]);
                split_pair(f1.z, f1.w, hw[3], lw[3]);
                int e = m * KP + ch + c;
                *(uint4*)&sAh[e] = *(uint4*)hw;
                *(uint4*)&sAl[e] = *(uint4*)lw;
            }
        }
        __syncthreads();

        float acc[2][8][4];
        #pragma unroll
        for (int mt = 0; mt < 2; mt++)
            #pragma unroll
            for (int nt = 0; nt < 8; nt++)
                #pragma unroll
                for (int j = 0; j < 4; j++) acc[mt][nt][j] = 0.f;

        #pragma unroll
        for (int ks = 0; ks < 4; ks++) {
            const int kb = ks * 16 + 2 * qt;
            uint32_t ah[2][4], al[2][4];
            #pragma unroll
            for (int mt = 0; mt < 2; mt++) {
                int e = (wm * 32 + mt * 16 + g) * KP + kb;
                ah[mt][0] = *(const uint32_t*)&sAh[e];
                ah[mt][1] = *(const uint32_t*)&sAh[e + 8 * KP];
                ah[mt][2] = *(const uint32_t*)&sAh[e + 8];
                ah[mt][3] = *(const uint32_t*)&sAh[e + 8 * KP + 8];
                al[mt][0] = *(const uint32_t*)&sAl[e];
                al[mt][1] = *(const uint32_t*)&sAl[e + 8 * KP];
                al[mt][2] = *(const uint32_t*)&sAl[e + 8];
                al[mt][3] = *(const uint32_t*)&sAl[e + 8 * KP + 8];
            }
            #pragma unroll
            for (int nt = 0; nt < 8; nt++) {
                int e = (wn * 64 + nt * 8 + g) * KP + kb;
                uint32_t bh[2], bl[2];
                bh[0] = *(const uint32_t*)&sWh[e];
                bh[1] = *(const uint32_t*)&sWh[e + 8];
                bl[0] = *(const uint32_t*)&sWl[e];
                bl[1] = *(const uint32_t*)&sWl[e + 8];
                mma_bf16(acc[0][nt], ah[0], bh);
                mma_bf16(acc[1][nt], ah[1], bh);
                mma_bf16(acc[0][nt], ah[0], bl);
                mma_bf16(acc[1][nt], ah[1], bl);
                mma_bf16(acc[0][nt], al[0], bh);
                mma_bf16(acc[1][nt], al[1], bh);
            }
        }

        #pragma unroll
        for (int mt = 0; mt < 2; mt++)
            #pragma unroll
            for (int nt = 0; nt < 8; nt++) {
                int rl = wm * 32 + mt * 16 + g;
                int col = wn * 64 + nt * 8 + 2 * qt;
                #pragma unroll
                for (int rh = 0; rh < 2; rh++) {
                    int gi = i0 + rl + rh * 8;
                    if (gi >= NN) continue;
                    float2 v = make_float2(acc[mt][nt][rh * 2] + sb1[col],
                                           acc[mt][nt][rh * 2 + 1] + sb1[col + 1]);
                    *(float2*)&Px[(size_t)gi * 128 + col] = v;
                }
            }
        __syncthreads();
    }
}

__global__ void __launch_bounds__(256, 1)
node_mma(const float* __restrict__ x_src, const float* __restrict__ a_src,
         const float* __restrict__ W1, const float* __restrict__ b1,
         const float* __restrict__ W2, const float* __restrict__ b2,
         float* __restrict__ dst, const float* __restrict__ inv, int count)
{
    extern __shared__ char smc[];
    uint16_t* sAh  = (uint16_t*)(smc + OFF_AH);
    uint16_t* sAl  = (uint16_t*)(smc + OFF_AL);
    uint16_t* sW1h = (uint16_t*)(smc + OFF_W1H);
    uint16_t* sW1l = (uint16_t*)(smc + OFF_W1L);
    uint16_t* sW2h = (uint16_t*)(smc + OFF_W2H);
    uint16_t* sW2l = (uint16_t*)(smc + OFF_W2L);
    float*    sb1  = (float*)(smc + OFF_B1);
    float*    sb2  = (float*)(smc + OFF_B2);

    const int tid = threadIdx.x;
    const int lane = tid & 31, w = tid >> 5;
    const int g = lane >> 2, qt = lane & 3;
    const int wm = w >> 1, wn = w & 1;

    {
        int n = tid & 127, k0 = (tid >> 7) * 64;
        for (int k = k0; k < k0 + 64; k += 2) {
            uint32_t hi, lo;
            split_pair(W1[k * 128 + n], W1[(k + 1) * 128 + n], hi, lo);
            *(uint32_t*)&sW1h[n * KP + k] = hi;
            *(uint32_t*)&sW1l[n * KP + k] = lo;
        }
    }
    {
        int n = tid & 63, k0 = (tid >> 6) * 32;
        for (int k = k0; k < k0 + 32; k += 2) {
            uint32_t hi, lo;
            split_pair(W2[k * 64 + n], W2[(k + 1) * 64 + n], hi, lo);
            *(uint32_t*)&sW2h[n * KP + k] = hi;
            *(uint32_t*)&sW2l[n * KP + k] = lo;
        }
    }
    if (tid < 128) sb1[tid] = b1[tid];
    if (tid < 64)  sb2[tid] = b2[tid];
    __syncthreads();

    for (int tile = blockIdx.x; tile < NT; tile += gridDim.x) {
        const int i0 = tile * 128;
        {
            const int m = tid & 127, half = tid >> 7;
            const int gi = i0 + m;
            const bool valid = gi < count;
            const float* src;
            float scale = 1.0f;
            bool doscale = false;
            if (half == 0) {
                src = x_src + (size_t)(valid ? gi : 0) * DD;
            } else {
                src = a_src + (size_t)(valid ? gi : 0) * DD;
                scale = valid ? inv[gi] : 0.0f;
                doscale = true;
            }
            #pragma unroll
            for (int c = 0; c < 64; c += 8) {
                float4 f0 = *(const float4*)(src + c);
                float4 f1 = *(const float4*)(src + c + 4);
                if (doscale) {
                    f0.x *= scale; f0.y *= scale; f0.z *= scale; f0.w *= scale;
                    f1.x *= scale; f1.y *= scale; f1.z *= scale; f1.w *= scale;
                }
                uint32_t hw[4], lw[4];
                split_pair(f0.x, f0.y, hw[0], lw[0]);
                split_pair(f0.z, f0.w, hw[1], lw[1]);
                split_pair(f1.x, f1.y, hw[2], lw[2]);
                split_pair(f1.z, f1.w, hw[3], lw[3]);
                int e = m * KP + half * 64 + c;
                *(uint4*)&sAh[e] = *(uint4*)hw;
                *(uint4*)&sAl[e] = *(uint4*)lw;
            }
        }
        __syncthreads();

        float acc[2][8][4];
        #pragma unroll
        for (int mt = 0; mt < 2; mt++)
            #pragma unroll
            for (int nt = 0; nt < 8; nt++)
                #pragma unroll
                for (int j = 0; j < 4; j++) acc[mt][nt][j] = 0.f;

        #pragma unroll
        for (int ks = 0; ks < 8; ks++) {
            const int kb = ks * 16 + 2 * qt;
            uint32_t ah[2][4], al[2][4];
            #pragma unroll
            for (int mt = 0; mt < 2; mt++) {
                int e = (wm * 32 + mt * 16 + g) * KP + kb;
                ah[mt][0] = *(const uint32_t*)&sAh[e];
                ah[mt][1] = *(const uint32_t*)&sAh[e + 8 * KP];
                ah[mt][2] = *(const uint32_t*)&sAh[e + 8];
                ah[mt][3] = *(const uint32_t*)&sAh[e + 8 * KP + 8];
                al[mt][0] = *(const uint32_t*)&sAl[e];
                al[mt][1] = *(const uint32_t*)&sAl[e + 8 * KP];
                al[mt][2] = *(const uint32_t*)&sAl[e + 8];
                al[mt][3] = *(const uint32_t*)&sAl[e + 8 * KP + 8];
            }
            #pragma unroll
            for (int nt = 0; nt < 8; nt++) {
                int e = (wn * 64 + nt * 8 + g) * KP + kb;
                uint32_t bh[2], bl[2];
                bh[0] = *(const uint32_t*)&sW1h[e];
                bh[1] = *(const uint32_t*)&sW1h[e + 8];
                bl[0] = *(const uint32_t*)&sW1l[e];
                bl[1] = *(const uint32_t*)&sW1l[e + 8];
                mma_bf16(acc[0][nt], ah[0], bh);
                mma_bf16(acc[1][nt], ah[1], bh);
                mma_bf16(acc[0][nt], ah[0], bl);
                mma_bf16(acc[1][nt], ah[1], bl);
                mma_bf16(acc[0][nt], al[0], bh);
                mma_bf16(acc[1][nt], al[1], bh);
            }
        }
        __syncthreads();

        #pragma unroll
        for (int mt = 0; mt < 2; mt++)
            #pragma unroll
            for (int nt = 0; nt < 8; nt++) {
                int row = wm * 32 + mt * 16 + g;
                int col = wn * 64 + nt * 8 + 2 * qt;
                float v0 = fmaxf(acc[mt][nt][0] + sb1[col], 0.f);
                float v1 = fmaxf(acc[mt][nt][1] + sb1[col + 1], 0.f);
                float v2 = fmaxf(acc[mt][nt][2] + sb1[col], 0.f);
                float v3 = fmaxf(acc[mt][nt][3] + sb1[col + 1], 0.f);
                uint32_t hi, lo;
                split_pair(v0, v1, hi, lo);
                *(uint32_t*)&sAh[row * KP + col] = hi;
                *(uint32_t*)&sAl[row * KP + col] = lo;
                split_pair(v2, v3, hi, lo);
                *(uint32_t*)&sAh[(row + 8) * KP + col] = hi;
                *(uint32_t*)&sAl[(row + 8) * KP + col] = lo;
            }
        __syncthreads();

        float acc2[2][4][4];
        #pragma unroll
        for (int mt = 0; mt < 2; mt++)
            #pragma unroll
            for (int nt = 0; nt < 4; nt++)
                #pragma unroll
                for (int j = 0; j < 4; j++) acc2[mt][nt][j] = 0.f;

        #pragma unroll
        for (int ks = 0; ks < 8; ks++) {
            const int kb = ks * 16 + 2 * qt;
            uint32_t ah[2][4], al[2][4];
            #pragma unroll
            for (int mt = 0; mt < 2; mt++) {
                int e = (wm * 32 + mt * 16 + g) * KP + kb;
                ah[mt][0] = *(const uint32_t*)&sAh[e];
                ah[mt][1] = *(const uint32_t*)&sAh[e + 8 * KP];
                ah[mt][2] = *(const uint32_t*)&sAh[e + 8];
                ah[mt][3] = *(const uint32_t*)&sAh[e + 8 * KP + 8];
                al[mt][0] = *(const uint32_t*)&sAl[e];
                al[mt][1] = *(const uint32_t*)&sAl[e + 8 * KP];
                al[mt][2] = *(const uint32_t*)&sAl[e + 8];
                al[mt][3] = *(const uint32_t*)&sAl[e + 8 * KP + 8];
            }
            #pragma unroll
            for (int nt = 0; nt < 4; nt++) {
                int e = (wn * 32 + nt * 8 + g) * KP + kb;
                uint32_t bh[2], bl[2];
                bh[0] = *(const uint32_t*)&sW2h[e];
                bh[1] = *(const uint32_t*)&sW2h[e + 8];
                bl[0] = *(const uint32_t*)&sW2l[e];
                bl[1] = *(const uint32_t*)&sW2l[e + 8];
                mma_bf16(acc2[0][nt], ah[0], bh);
                mma_bf16(acc2[1][nt], ah[1], bh);
                mma_bf16(acc2[0][nt], ah[0], bl);
                mma_bf16(acc2[1][nt], ah[1], bl);
                mma_bf16(acc2[0][nt], al[0], bh);
                mma_bf16(acc2[1][nt], al[1], bh);
            }
        }

        #pragma unroll
        for (int mt = 0; mt < 2; mt++)
            #pragma unroll
            for (int nt = 0; nt < 4; nt++) {
                int rl = wm * 32 + mt * 16 + g;
                int col = wn * 32 + nt * 8 + 2 * qt;
                #pragma unroll
                for (int rh = 0; rh < 2; rh++) {
                    int row = rl + rh * 8;
                    int gi = i0 + row;
                    if (gi >= count) continue;
                    float vx = acc2[mt][nt][rh * 2 + 0] + sb2[col];
                    float vy = acc2[mt][nt][rh * 2 + 1] + sb2[col + 1];
                    float2 rv = *(const float2*)(x_src + (size_t)gi * DD + col);
                    *(float2*)(dst + (size_t)gi * DD + col) =
                        make_float2(rv.x + vx, rv.y + vy);
                }
            }
        __syncthreads();
    }
}

extern "C" void kernel_launch(void* const* d_in, const int* in_sizes, int n_in,
                              void* d_out, int out_size)
{
    const float* x   = (const float*)d_in[0];
    const float* ea  = (const float*)d_in[1];
    const float* We1 = (const float*)d_in[2];
    const float* be1 = (const float*)d_in[3];
    const float* We2 = (const float*)d_in[4];
    const float* be2 = (const float*)d_in[5];
    const float* Wn1 = (const float*)d_in[6];
    const float* bn1 = (const float*)d_in[7];
    const float* Wn2 = (const float*)d_in[8];
    const float* bn2 = (const float*)d_in[9];
    const void*  eidx = d_in[10];

    float* out_x  = (float*)d_out;
    float* out_ea = (float*)d_out + (size_t)NN * DD;

    float *agg, *inv, *Wc, *Px;
    int* cnt;
    cudaGetSymbolAddress((void**)&agg, g_agg);
    cudaGetSymbolAddress((void**)&inv, g_inv);
    cudaGetSymbolAddress((void**)&cnt, g_cnt);
    cudaGetSymbolAddress((void**)&Wc,  g_Wc);
    cudaGetSymbolAddress((void**)&Px,  g_Px);

    cudaFuncSetAttribute(edge_mma, cudaFuncAttributeMaxDynamicSharedMemorySize, E_SMEM);
    cudaFuncSetAttribute(node_mma, cudaFuncAttributeMaxDynamicSharedMemorySize, SMEMSZ);
    cudaFuncSetAttribute(px_k,     cudaFuncAttributeMaxDynamicSharedMemorySize, SMEMSZ);

    int smcount = 148;
    cudaDeviceGetAttribute(&smcount, cudaDevAttrMultiProcessorCount, 0);
    int ge = 2 * smcount < ET ? 2 * smcount : ET;
    int gn = smcount < NT ? smcount : NT;

    // Edge kernel is my 4th launch (global #6 with harness prelaunches; -s 5 window).
    prolog_k<<<(NN * DD / 4 + 255) / 256, 256>>>(eidx, agg, cnt);        // 0
    combine_w_k<<<(128 * 128 + 255) / 256, 256>>>(We1, Wc);              // 1
    px_k<<<gn, 256, SMEMSZ>>>(x, Wc, be1, Px);                           // 2
    edge_mma<<<ge, 256, E_SMEM>>>(ea, eidx, Px, Wc, We2, be2,            // 3 <- profiled
                                  out_ea, agg, ET);
    count_k<<<(EE + 255) / 256, 256>>>(eidx, cnt);                       // 4
    inv_k<<<(NN + 255) / 256, 256>>>(cnt, inv);                          // 5
    node_mma<<<gn, 256, SMEMSZ>>>(x, agg, Wn1, bn1, Wn2, bn2,            // 6
                                  out_x, inv, NN);

    // iteration 2
    zero_f4<<<(NN * DD / 4 + 255) / 256, 256>>>(agg, NN * DD / 4);
    px_k<<<gn, 256, SMEMSZ>>>(out_x, Wc, be1, Px);
    edge_mma<<<ge, 256, E_SMEM>>>(out_ea, eidx, Px, Wc, We2, be2,
                                  out_ea, agg, ET);
    node_mma<<<gn, 256, SMEMSZ>>>(out_x, agg, Wn1, bn1, Wn2, bn2,
                                  out_x, inv, NN);
}

// round 11
// speedup vs baseline: 1.1411x; 1.0023x over previous
#include <cuda_runtime.h>
#include <cuda_bf16.h>
#include <cstdint>

#define NN 50000
#define EE 800000
#define DD 64
#define ET 6250                 // EE / 128
#define NT 391                  // ceil(NN / 128)
#define KP 136                  // node-kernel padded K stride (bf16)

// ---------------- device-global scratch (no allocations allowed) ----------
__device__ float g_agg[NN * DD];
__device__ float g_inv[NN];
__device__ int   g_cnt[NN];
__device__ float g_Wc[128 * 128];
__device__ float g_Px[NN * 128];   // per-node x @ Wc[0:64] + be1
__device__ int   g_is64;

__device__ __forceinline__ int load_row(const void* eidx, int i) {
    if (g_is64) return (int)((const long long*)eidx)[i];
    return ((const int*)eidx)[i];
}

__global__ void prolog_k(const void* eidx, float* agg, int* cnt) {
    int i = blockIdx.x * blockDim.x + threadIdx.x;
    if (i < NN * DD / 4) ((float4*)agg)[i] = make_float4(0.f, 0.f, 0.f, 0.f);
    if (i < NN) cnt[i] = 0;
    if (i == 0) {
        const long long* p = (const long long*)eidx;
        int ok = 1;
        for (int j = 0; j < 64; j++) {
            long long v = p[j];
            if (v < 0 || v >= NN) { ok = 0; break; }
        }
        g_is64 = ok;
    }
}

__global__ void combine_w_k(const float* __restrict__ We1, float* __restrict__ Wc) {
    int i = blockIdx.x * blockDim.x + threadIdx.x;
    if (i < 128 * 128) {
        int k = i >> 7, n = i & 127;
        float v = We1[(k + 64) * 128 + n];
        if (k < 64) v += We1[k * 128 + n];
        Wc[i] = v;
    }
}

__global__ void zero_f4(float* p, int n4) {
    int i = blockIdx.x * blockDim.x + threadIdx.x;
    if (i < n4) ((float4*)p)[i] = make_float4(0.f, 0.f, 0.f, 0.f);
}
__global__ void count_k(const void* eidx, int* cnt) {
    int i = blockIdx.x * blockDim.x + threadIdx.x;
    if (i < EE) atomicAdd(&cnt[load_row(eidx, i)], 1);
}
__global__ void inv_k(const int* __restrict__ cnt, float* __restrict__ inv) {
    int i = blockIdx.x * blockDim.x + threadIdx.x;
    if (i < NN) inv[i] = 1.0f / fmaxf((float)cnt[i], 1.0f);
}

// ---------------- helpers ---------------------------------------------------
// Fast bf16 split-2: packed cvt.rn.bf16x2.f32 (sm_80+ PTX).
__device__ __forceinline__ void split_pair(float f0, float f1, uint32_t& hi, uint32_t& lo) {
    asm("cvt.rn.bf16x2.f32 %0, %1, %2;" : "=r"(hi) : "f"(f1), "f"(f0));
    float h0 = __uint_as_float(hi << 16);
    float h1 = __uint_as_float(hi & 0xFFFF0000u);
    float r0 = f0 - h0;
    float r1 = f1 - h1;
    asm("cvt.rn.bf16x2.f32 %0, %1, %2;" : "=r"(lo) : "f"(r1), "f"(r0));
}

// m16n8k16 row.col bf16 -> f32 accumulate (baseline PTX, sm_80+)
__device__ __forceinline__ void mma_bf16(float* d, const uint32_t* a, const uint32_t* b) {
    asm volatile(
        "mma.sync.aligned.m16n8k16.row.col.f32.bf16.bf16.f32 "
        "{%0,%1,%2,%3}, {%4,%5,%6,%7}, {%8,%9}, {%0,%1,%2,%3};"
        : "+f"(d[0]), "+f"(d[1]), "+f"(d[2]), "+f"(d[3])
        : "r"(a[0]), "r"(a[1]), "r"(a[2]), "r"(a[3]), "r"(b[0]), "r"(b[1]));
}

// ================= EDGE KERNEL =============================================
// Fragment block (16B) per (row, ks, qt): {hi(k2,k2+1), hi(k2+8,k2+9),
// lo(k2,k2+1), lo(k2+8,k2+9)}, k2 = 16ks+2qt. Swizzles phase-verified
// conflict-free for both reads (8 lanes = 2 g x 4 qt) and writes (8 lanes =
// 8 consecutive rows).
#define E_SA   0                  // 32KB: raw ea -> blocked A -> D2 staging
#define E_SW1  32768              // W1: 128 rows x 256B (K=64)
#define E_SW2  65536              // W2:  64 rows x 512B (K=128)
#define E_B2   98304              // 64 f32
#define E_RW   98560              // 128 int rows
#define E_SMEM 99072

__device__ __forceinline__ uint32_t addr64(int row, int ks, int qt) {   // 256B/row
    uint32_t chunk = ((uint32_t)((ks ^ (row & 3)) & 3) << 2)
                   | (uint32_t)((qt ^ ((row >> 2) & 3)) & 3);
    return ((uint32_t)row << 8) + (chunk << 4);
}
__device__ __forceinline__ uint32_t addr128k(int row, int ks, int qt) { // 512B/row
    uint32_t chunk = ((uint32_t)((ks ^ (row & 7)) & 7) << 2)
                   | (uint32_t)((qt ^ ((row >> 3) & 3)) & 3);
    return ((uint32_t)row << 9) + (chunk << 4);
}
// raw 16B-chunk swizzle within a 256B row (16 chunks)
__device__ __forceinline__ uint32_t addr_raw(int row, int c) {
    return ((uint32_t)row << 8) + ((uint32_t)((c ^ (row & 15)) & 15) << 4);
}

__global__ void __launch_bounds__(256, 2)
edge_mma(const float* __restrict__ ea, const void* __restrict__ eidx,
         const float* __restrict__ Px,
         const float* __restrict__ Wc, const float* __restrict__ W2,
         const float* __restrict__ b2,
         float* __restrict__ dst, float* __restrict__ agg, int ntiles)
{
    extern __shared__ char smc[];
    float* sb2  = (float*)(smc + E_B2);
    int*   sRows = (int*)(smc + E_RW);

    const int tid = threadIdx.x;
    const int lane = tid & 31, w = tid >> 5;
    const int g = lane >> 2, qt = lane & 3;

    // ---- stage W1 = Wc rows 64:127 (K=64) in fragment blocks ----
    {
        const int n = tid & 127, h = tid >> 7;
        uint32_t hi[16], lo[16];
        #pragma unroll
        for (int p = 0; p < 16; p++) {
            int k = 32 * h + 2 * p;
            split_pair(Wc[(64 + k) * 128 + n], Wc[(64 + k + 1) * 128 + n], hi[p], lo[p]);
        }
        #pragma unroll
        for (int j = 0; j < 2; j++)
            #pragma unroll
            for (int q = 0; q < 4; q++) {
                uint4 blk = make_uint4(hi[8 * j + q], hi[8 * j + q + 4],
                                       lo[8 * j + q], lo[8 * j + q + 4]);
                *(uint4*)(smc + E_SW1 + addr64(n, 2 * h + j, q)) = blk;
            }
    }
    // ---- stage W2 (64n x K=128) in fragment blocks ----
    {
        const int n = tid & 63, kq = tid >> 6;
        uint32_t hi[16], lo[16];
        #pragma unroll
        for (int p = 0; p < 16; p++) {
            int k = 32 * kq + 2 * p;
            split_pair(W2[k * 64 + n], W2[(k + 1) * 64 + n], hi[p], lo[p]);
        }
        #pragma unroll
        for (int j = 0; j < 2; j++)
            #pragma unroll
            for (int q = 0; q < 4; q++) {
                uint4 blk = make_uint4(hi[8 * j + q], hi[8 * j + q + 4],
                                       lo[8 * j + q], lo[8 * j + q + 4]);
                *(uint4*)(smc + E_SW2 + addr128k(n, 2 * kq + j, q)) = blk;
            }
    }
    if (tid < 64) sb2[tid] = b2[tid];
    __syncthreads();

    for (int tile = blockIdx.x; tile < ntiles; tile += gridDim.x) {
        const int i0 = tile * 128;
        const int mrow0 = 16 * w + g;

        if (tid < 128) sRows[tid] = load_row(eidx, i0 + tid);
        const int r0 = load_row(eidx, i0 + mrow0);
        const int r1 = load_row(eidx, i0 + mrow0 + 8);

        // ---- A-build phase 1: coalesced raw copy of ea tile into sA ----
        {
            const uint4* src = (const uint4*)(ea + (size_t)i0 * DD);
            #pragma unroll
            for (int p = 0; p < 8; p++) {
                int id = p * 256 + tid;
                uint4 v = src[id];
                *(uint4*)(smc + E_SA + addr_raw(id >> 4, id & 15)) = v;
            }
        }
        __syncthreads();

        // ---- phase 2: read own half-row from raw ----
        const int m = tid & 127, h = tid >> 7;
        uint4 raw[8];
        #pragma unroll
        for (int j = 0; j < 8; j++)
            raw[j] = *(const uint4*)(smc + E_SA + addr_raw(m, 8 * h + j));
        __syncthreads();   // all raw reads done before blocked writes

        // ---- phase 3: convert + blocked STS ----
        {
            uint32_t hiP[8][2], loP[8][2];
            #pragma unroll
            for (int j = 0; j < 8; j++) {
                float f0 = __uint_as_float(raw[j].x);
                float f1 = __uint_as_float(raw[j].y);
                float f2 = __uint_as_float(raw[j].z);
                float f3 = __uint_as_float(raw[j].w);
                split_pair(f0, f1, hiP[j][0], loP[j][0]);
                split_pair(f2, f3, hiP[j][1], loP[j][1]);
            }
            #pragma unroll
            for (int ksl = 0; ksl < 2; ksl++)
                #pragma unroll
                for (int q = 0; q < 4; q++) {
                    int j = 4 * ksl + (q >> 1), e = q & 1;
                    uint4 blk = make_uint4(hiP[j][e], hiP[j + 2][e],
                                           loP[j][e], loP[j + 2][e]);
                    *(uint4*)(smc + E_SA + addr64(m, 2 * h + ksl, q)) = blk;
                }
        }

        // ---- init acc1 from Px gather (be1 folded into Px) ----
        float acc1[16][4];
        #pragma unroll
        for (int nt = 0; nt < 16; nt++) {
            int col = 8 * nt + 2 * qt;
            float2 v0 = *(const float2*)&Px[(size_t)r0 * 128 + col];
            float2 v1 = *(const float2*)&Px[(size_t)r1 * 128 + col];
            acc1[nt][0] = v0.x; acc1[nt][1] = v0.y;
            acc1[nt][2] = v1.x; acc1[nt][3] = v1.y;
        }
        __syncthreads();

        // ---- GEMM1: acc1 += ea @ W1 (K=64, 3 split terms) ----
        #pragma unroll
        for (int ks = 0; ks < 4; ks++) {
            uint4 A0 = *(const uint4*)(smc + E_SA + addr64(mrow0, ks, qt));
            uint4 A1 = *(const uint4*)(smc + E_SA + addr64(mrow0 + 8, ks, qt));
            uint32_t ah[4] = {A0.x, A1.x, A0.y, A1.y};
            uint32_t al[4] = {A0.z, A1.z, A0.w, A1.w};
            #pragma unroll
            for (int nt = 0; nt < 16; nt++) {
                uint4 B = *(const uint4*)(smc + E_SW1 + addr64(8 * nt + g, ks, qt));
                uint32_t bh[2] = {B.x, B.y}, bl[2] = {B.z, B.w};
                mma_bf16(acc1[nt], ah, bh);
                mma_bf16(acc1[nt], ah, bl);
                mma_bf16(acc1[nt], al, bh);
            }
        }
        __syncthreads();   // sA reads done -> reusable for D2 staging

        // ---- pack H fragments (relu fused); acc1 dies here ----
        uint32_t hA[8][4], lA[8][4];
        #pragma unroll
        for (int ks = 0; ks < 8; ks++) {
            float v00 = fmaxf(acc1[2 * ks][0], 0.f);
            float v01 = fmaxf(acc1[2 * ks][1], 0.f);
            float v02 = fmaxf(acc1[2 * ks][2], 0.f);
            float v03 = fmaxf(acc1[2 * ks][3], 0.f);
            float v10 = fmaxf(acc1[2 * ks + 1][0], 0.f);
            float v11 = fmaxf(acc1[2 * ks + 1][1], 0.f);
            float v12 = fmaxf(acc1[2 * ks + 1][2], 0.f);
            float v13 = fmaxf(acc1[2 * ks + 1][3], 0.f);
            split_pair(v00, v01, hA[ks][0], lA[ks][0]);
            split_pair(v02, v03, hA[ks][1], lA[ks][1]);
            split_pair(v10, v11, hA[ks][2], lA[ks][2]);
            split_pair(v12, v13, hA[ks][3], lA[ks][3]);
        }

        // ---- GEMM2: acc2 = H @ W2 (K=128) from packed registers ----
        float acc2[8][4];
        #pragma unroll
        for (int nt = 0; nt < 8; nt++)
            #pragma unroll
            for (int j = 0; j < 4; j++) acc2[nt][j] = 0.f;

        #pragma unroll
        for (int ks = 0; ks < 8; ks++) {
            #pragma unroll
            for (int nt = 0; nt < 8; nt++) {
                uint4 B = *(const uint4*)(smc + E_SW2 + addr128k(8 * nt + g, ks, qt));
                uint32_t bh[2] = {B.x, B.y}, bl[2] = {B.z, B.w};
                mma_bf16(acc2[nt], hA[ks], bh);
                mma_bf16(acc2[nt], hA[ks], bl);
                mma_bf16(acc2[nt], lA[ks], bh);
            }
        }

        // ---- stage D2 into sA: float2 at swizzled (row, chunk, slot) ----
        // chunk c = 2nt+(qt>>1) -> physical (c ^ (row&15)); slot s = qt&1 ->
        // physical offset 8*(s ^ (row&1)). Phase-verified conflict-free.
        #pragma unroll
        for (int nt = 0; nt < 8; nt++) {
            int c = 2 * nt + (qt >> 1), s = qt & 1;
            {
                int r = mrow0;
                uint32_t a = (uint32_t)(r << 8) + ((uint32_t)((c ^ (r & 15)) & 15) << 4)
                           + ((uint32_t)(s ^ (r & 1)) << 3);
                *(float2*)(smc + E_SA + a) = make_float2(acc2[nt][0], acc2[nt][1]);
            }
            {
                int r = mrow0 + 8;
                uint32_t a = (uint32_t)(r << 8) + ((uint32_t)((c ^ (r & 15)) & 15) << 4)
                           + ((uint32_t)(s ^ (r & 1)) << 3);
                *(float2*)(smc + E_SA + a) = make_float2(acc2[nt][2], acc2[nt][3]);
            }
        }
        __syncthreads();

        // ---- coalesced epilogue: red.v4 agg; dst = ea + (D2 + b2) ----
        {
            const float4* easrc = (const float4*)(ea + (size_t)i0 * DD);
            float4* dstp = (float4*)(dst + (size_t)i0 * DD);
            #pragma unroll
            for (int p = 0; p < 8; p++) {
                int id = p * 256 + tid;
                int row = id >> 4, c = id & 15;
                uint4 d = *(const uint4*)(smc + E_SA + addr_raw(row, c));
                float2 a = make_float2(__uint_as_float(d.x), __uint_as_float(d.y));
                float2 b = make_float2(__uint_as_float(d.z), __uint_as_float(d.w));
                if (row & 1) { float2 t = a; a = b; b = t; }
                float4 v;
                v.x = a.x + sb2[4 * c + 0];
                v.y = a.y + sb2[4 * c + 1];
                v.z = b.x + sb2[4 * c + 2];
                v.w = b.y + sb2[4 * c + 3];
                float* ap = agg + (size_t)sRows[row] * DD + 4 * c;
                asm volatile("red.global.add.v4.f32 [%0], {%1, %2, %3, %4};"
                             :: "l"(ap), "f"(v.x), "f"(v.y), "f"(v.z), "f"(v.w)
                             : "memory");
                float4 e = easrc[id];
                float4 o = make_float4(e.x + v.x, e.y + v.y, e.z + v.z, e.w + v.w);
                dstp[id] = o;
            }
        }
        __syncthreads();   // D2 reads done before next tile's raw copy
    }
}

// ---------------- node / px kernels (round-10, known good) -----------------
#define OFF_AH   0
#define OFF_AL   34816
#define OFF_W1H  69632
#define OFF_W1L  104448
#define OFF_W2H  139264
#define OFF_W2L  156672
#define OFF_B1   174080
#define OFF_B2   174592
#define SMEMSZ   175360

__global__ void __launch_bounds__(256, 1)
px_k(const float* __restrict__ x, const float* __restrict__ Wc,
     const float* __restrict__ be1, float* __restrict__ Px)
{
    extern __shared__ char smc[];
    uint16_t* sAh = (uint16_t*)(smc + OFF_AH);
    uint16_t* sAl = (uint16_t*)(smc + OFF_AL);
    uint16_t* sWh = (uint16_t*)(smc + OFF_W1H);
    uint16_t* sWl = (uint16_t*)(smc + OFF_W1L);
    float*    sb1 = (float*)(smc + OFF_B1);

    const int tid = threadIdx.x;
    const int lane = tid & 31, w = tid >> 5;
    const int g = lane >> 2, qt = lane & 3;
    const int wm = w >> 1, wn = w & 1;

    {
        int n = tid & 127, k0 = (tid >> 7) * 32;
        for (int k = k0; k < k0 + 32; k += 2) {
            uint32_t hi, lo;
            split_pair(Wc[k * 128 + n], Wc[(k + 1) * 128 + n], hi, lo);
            *(uint32_t*)&sWh[n * KP + k] = hi;
            *(uint32_t*)&sWl[n * KP + k] = lo;
        }
    }
    if (tid < 128) sb1[tid] = be1[tid];
    __syncthreads();

    for (int tile = blockIdx.x; tile < NT; tile += gridDim.x) {
        const int i0 = tile * 128;
        {
            const int m = tid & 127, ch = (tid >> 7) * 32;
            const int gi = i0 + m;
            const bool valid = gi < NN;
            const float* src = x + (size_t)(valid ? gi : 0) * DD + ch;
            #pragma unroll
            for (int c = 0; c < 32; c += 8) {
                float4 f0, f1;
                if (valid) { f0 = *(const float4*)(src + c); f1 = *(const float4*)(src + c + 4); }
                else { f0 = make_float4(0,0,0,0); f1 = f0; }
                uint32_t hw[4], lw[4];
                split_pair(f0.x, f0.y, hw[0], lw[0]);
                split_pair(f0.z, f0.w, hw[1], lw[1]);
                split_pair(f1.x, f1.y, hw[2], lw[2]);
                split_pair(f1.z, f1.w, hw[3], lw[3]);
                int e = m * KP + ch + c;
                *(uint4*)&sAh[e] = *(uint4*)hw;
                *(uint4*)&sAl[e] = *(uint4*)lw;
            }
        }
        __syncthreads();

        float acc[2][8][4];
        #pragma unroll
        for (int mt = 0; mt < 2; mt++)
            #pragma unroll
            for (int nt = 0; nt < 8; nt++)
                #pragma unroll
                for (int j = 0; j < 4; j++) acc[mt][nt][j] = 0.f;

        #pragma unroll
        for (int ks = 0; ks < 4; ks++) {
            const int kb = ks * 16 + 2 * qt;
            uint32_t ah[2][4], al[2][4];
            #pragma unroll
            for (int mt = 0; mt < 2; mt++) {
                int e = (wm * 32 + mt * 16 + g) * KP + kb;
                ah[mt][0] = *(const uint32_t*)&sAh[e];
                ah[mt][1] = *(const uint32_t*)&sAh[e + 8 * KP];
                ah[mt][2] = *(const uint32_t*)&sAh[e + 8];
                ah[mt][3] = *(const uint32_t*)&sAh[e + 8 * KP + 8];
                al[mt][0] = *(const uint32_t*)&sAl[e];
                al[mt][1] = *(const uint32_t*)&sAl[e + 8 * KP];
                al[mt][2] = *(const uint32_t*)&sAl[e + 8];
                al[mt][3] = *(const uint32_t*)&sAl[e + 8 * KP + 8];
            }
            #pragma unroll
            for (int nt = 0; nt < 8; nt++) {
                int e = (wn * 64 + nt * 8 + g) * KP + kb;
                uint32_t bh[2], bl[2];
                bh[0] = *(const uint32_t*)&sWh[e];
                bh[1] = *(const uint32_t*)&sWh[e + 8];
                bl[0] = *(const uint32_t*)&sWl[e];
                bl[1] = *(const uint32_t*)&sWl[e + 8];
                mma_bf16(acc[0][nt], ah[0], bh);
                mma_bf16(acc[1][nt], ah[1], bh);
                mma_bf16(acc[0][nt], ah[0], bl);
                mma_bf16(acc[1][nt], ah[1], bl);
                mma_bf16(acc[0][nt], al[0], bh);
                mma_bf16(acc[1][nt], al[1], bh);
            }
        }

        #pragma unroll
        for (int mt = 0; mt < 2; mt++)
            #pragma unroll
            for (int nt = 0; nt < 8; nt++) {
                int rl = wm * 32 + mt * 16 + g;
                int col = wn * 64 + nt * 8 + 2 * qt;
                #pragma unroll
                for (int rh = 0; rh < 2; rh++) {
                    int gi = i0 + rl + rh * 8;
                    if (gi >= NN) continue;
                    float2 v = make_float2(acc[mt][nt][rh * 2] + sb1[col],
                                           acc[mt][nt][rh * 2 + 1] + sb1[col + 1]);
                    *(float2*)&Px[(size_t)gi * 128 + col] = v;
                }
            }
        __syncthreads();
    }
}

__global__ void __launch_bounds__(256, 1)
node_mma(const float* __restrict__ x_src, const float* __restrict__ a_src,
         const float* __restrict__ W1, const float* __restrict__ b1,
         const float* __restrict__ W2, const float* __restrict__ b2,
         float* __restrict__ dst, const float* __restrict__ inv, int count)
{
    extern __shared__ char smc[];
    uint16_t* sAh  = (uint16_t*)(smc + OFF_AH);
    uint16_t* sAl  = (uint16_t*)(smc + OFF_AL);
    uint16_t* sW1h = (uint16_t*)(smc + OFF_W1H);
    uint16_t* sW1l = (uint16_t*)(smc + OFF_W1L);
    uint16_t* sW2h = (uint16_t*)(smc + OFF_W2H);
    uint16_t* sW2l = (uint16_t*)(smc + OFF_W2L);
    float*    sb1  = (float*)(smc + OFF_B1);
    float*    sb2  = (float*)(smc + OFF_B2);

    const int tid = threadIdx.x;
    const int lane = tid & 31, w = tid >> 5;
    const int g = lane >> 2, qt = lane & 3;
    const int wm = w >> 1, wn = w & 1;

    {
        int n = tid & 127, k0 = (tid >> 7) * 64;
        for (int k = k0; k < k0 + 64; k += 2) {
            uint32_t hi, lo;
            split_pair(W1[k * 128 + n], W1[(k + 1) * 128 + n], hi, lo);
            *(uint32_t*)&sW1h[n * KP + k] = hi;
            *(uint32_t*)&sW1l[n * KP + k] = lo;
        }
    }
    {
        int n = tid & 63, k0 = (tid >> 6) * 32;
        for (int k = k0; k < k0 + 32; k += 2) {
            uint32_t hi, lo;
            split_pair(W2[k * 64 + n], W2[(k + 1) * 64 + n], hi, lo);
            *(uint32_t*)&sW2h[n * KP + k] = hi;
            *(uint32_t*)&sW2l[n * KP + k] = lo;
        }
    }
    if (tid < 128) sb1[tid] = b1[tid];
    if (tid < 64)  sb2[tid] = b2[tid];
    __syncthreads();

    for (int tile = blockIdx.x; tile < NT; tile += gridDim.x) {
        const int i0 = tile * 128;
        {
            const int m = tid & 127, half = tid >> 7;
            const int gi = i0 + m;
            const bool valid = gi < count;
            const float* src;
            float scale = 1.0f;
            bool doscale = false;
            if (half == 0) {
                src = x_src + (size_t)(valid ? gi : 0) * DD;
            } else {
                src = a_src + (size_t)(valid ? gi : 0) * DD;
                scale = valid ? inv[gi] : 0.0f;
                doscale = true;
            }
            #pragma unroll
            for (int c = 0; c < 64; c += 8) {
                float4 f0 = *(const float4*)(src + c);
                float4 f1 = *(const float4*)(src + c + 4);
                if (doscale) {
                    f0.x *= scale; f0.y *= scale; f0.z *= scale; f0.w *= scale;
                    f1.x *= scale; f1.y *= scale; f1.z *= scale; f1.w *= scale;
                }
                uint32_t hw[4], lw[4];
                split_pair(f0.x, f0.y, hw[0], lw[0]);
                split_pair(f0.z, f0.w, hw[1], lw[1]);
                split_pair(f1.x, f1.y, hw[2], lw[2]);
                split_pair(f1.z, f1.w, hw[3], lw[3]);
                int e = m * KP + half * 64 + c;
                *(uint4*)&sAh[e] = *(uint4*)hw;
                *(uint4*)&sAl[e] = *(uint4*)lw;
            }
        }
        __syncthreads();

        float acc[2][8][4];
        #pragma unroll
        for (int mt = 0; mt < 2; mt++)
            #pragma unroll
            for (int nt = 0; nt < 8; nt++)
                #pragma unroll
                for (int j = 0; j < 4; j++) acc[mt][nt][j] = 0.f;

        #pragma unroll
        for (int ks = 0; ks < 8; ks++) {
            const int kb = ks * 16 + 2 * qt;
            uint32_t ah[2][4], al[2][4];
            #pragma unroll
            for (int mt = 0; mt < 2; mt++) {
                int e = (wm * 32 + mt * 16 + g) * KP + kb;
                ah[mt][0] = *(const uint32_t*)&sAh[e];
                ah[mt][1] = *(const uint32_t*)&sAh[e + 8 * KP];
                ah[mt][2] = *(const uint32_t*)&sAh[e + 8];
                ah[mt][3] = *(const uint32_t*)&sAh[e + 8 * KP + 8];
                al[mt][0] = *(const uint32_t*)&sAl[e];
                al[mt][1] = *(const uint32_t*)&sAl[e + 8 * KP];
                al[mt][2] = *(const uint32_t*)&sAl[e + 8];
                al[mt][3] = *(const uint32_t*)&sAl[e + 8 * KP + 8];
            }
            #pragma unroll
            for (int nt = 0; nt < 8; nt++) {
                int e = (wn * 64 + nt * 8 + g) * KP + kb;
                uint32_t bh[2], bl[2];
                bh[0] = *(const uint32_t*)&sW1h[e];
                bh[1] = *(const uint32_t*)&sW1h[e + 8];
                bl[0] = *(const uint32_t*)&sW1l[e];
                bl[1] = *(const uint32_t*)&sW1l[e + 8];
                mma_bf16(acc[0][nt], ah[0], bh);
                mma_bf16(acc[1][nt], ah[1], bh);
                mma_bf16(acc[0][nt], ah[0], bl);
                mma_bf16(acc[1][nt], ah[1], bl);
                mma_bf16(acc[0][nt], al[0], bh);
                mma_bf16(acc[1][nt], al[1], bh);
            }
        }
        __syncthreads();

        #pragma unroll
        for (int mt = 0; mt < 2; mt++)
            #pragma unroll
            for (int nt = 0; nt < 8; nt++) {
                int row = wm * 32 + mt * 16 + g;
                int col = wn * 64 + nt * 8 + 2 * qt;
                float v0 = fmaxf(acc[mt][nt][0] + sb1[col], 0.f);
                float v1 = fmaxf(acc[mt][nt][1] + sb1[col + 1], 0.f);
                float v2 = fmaxf(acc[mt][nt][2] + sb1[col], 0.f);
                float v3 = fmaxf(acc[mt][nt][3] + sb1[col + 1], 0.f);
                uint32_t hi, lo;
                split_pair(v0, v1, hi, lo);
                *(uint32_t*)&sAh[row * KP + col] = hi;
                *(uint32_t*)&sAl[row * KP + col] = lo;
                split_pair(v2, v3, hi, lo);
                *(uint32_t*)&sAh[(row + 8) * KP + col] = hi;
                *(uint32_t*)&sAl[(row + 8) * KP + col] = lo;
            }
        __syncthreads();

        float acc2[2][4][4];
        #pragma unroll
        for (int mt = 0; mt < 2; mt++)
            #pragma unroll
            for (int nt = 0; nt < 4; nt++)
                #pragma unroll
                for (int j = 0; j < 4; j++) acc2[mt][nt][j] = 0.f;

        #pragma unroll
        for (int ks = 0; ks < 8; ks++) {
            const int kb = ks * 16 + 2 * qt;
            uint32_t ah[2][4], al[2][4];
            #pragma unroll
            for (int mt = 0; mt < 2; mt++) {
                int e = (wm * 32 + mt * 16 + g) * KP + kb;
                ah[mt][0] = *(const uint32_t*)&sAh[e];
                ah[mt][1] = *(const uint32_t*)&sAh[e + 8 * KP];
                ah[mt][2] = *(const uint32_t*)&sAh[e + 8];
                ah[mt][3] = *(const uint32_t*)&sAh[e + 8 * KP + 8];
                al[mt][0] = *(const uint32_t*)&sAl[e];
                al[mt][1] = *(const uint32_t*)&sAl[e + 8 * KP];
                al[mt][2] = *(const uint32_t*)&sAl[e + 8];
                al[mt][3] = *(const uint32_t*)&sAl[e + 8 * KP + 8];
            }
            #pragma unroll
            for (int nt = 0; nt < 4; nt++) {
                int e = (wn * 32 + nt * 8 + g) * KP + kb;
                uint32_t bh[2], bl[2];
                bh[0] = *(const uint32_t*)&sW2h[e];
                bh[1] = *(const uint32_t*)&sW2h[e + 8];
                bl[0] = *(const uint32_t*)&sW2l[e];
                bl[1] = *(const uint32_t*)&sW2l[e + 8];
                mma_bf16(acc2[0][nt], ah[0], bh);
                mma_bf16(acc2[1][nt], ah[1], bh);
                mma_bf16(acc2[0][nt], ah[0], bl);
                mma_bf16(acc2[1][nt], ah[1], bl);
                mma_bf16(acc2[0][nt], al[0], bh);
                mma_bf16(acc2[1][nt], al[1], bh);
            }
        }

        #pragma unroll
        for (int mt = 0; mt < 2; mt++)
            #pragma unroll
            for (int nt = 0; nt < 4; nt++) {
                int rl = wm * 32 + mt * 16 + g;
                int col = wn * 32 + nt * 8 + 2 * qt;
                #pragma unroll
                for (int rh = 0; rh < 2; rh++) {
                    int row = rl + rh * 8;
                    int gi = i0 + row;
                    if (gi >= count) continue;
                    float vx = acc2[mt][nt][rh * 2 + 0] + sb2[col];
                    float vy = acc2[mt][nt][rh * 2 + 1] + sb2[col + 1];
                    float2 rv = *(const float2*)(x_src + (size_t)gi * DD + col);
                    *(float2*)(dst + (size_t)gi * DD + col) =
                        make_float2(rv.x + vx, rv.y + vy);
                }
            }
        __syncthreads();
    }
}

extern "C" void kernel_launch(void* const* d_in, const int* in_sizes, int n_in,
                              void* d_out, int out_size)
{
    const float* x   = (const float*)d_in[0];
    const float* ea  = (const float*)d_in[1];
    const float* We1 = (const float*)d_in[2];
    const float* be1 = (const float*)d_in[3];
    const float* We2 = (const float*)d_in[4];
    const float* be2 = (const float*)d_in[5];
    const float* Wn1 = (const float*)d_in[6];
    const float* bn1 = (const float*)d_in[7];
    const float* Wn2 = (const float*)d_in[8];
    const float* bn2 = (const float*)d_in[9];
    const void*  eidx = d_in[10];

    float* out_x  = (float*)d_out;
    float* out_ea = (float*)d_out + (size_t)NN * DD;

    float *agg, *inv, *Wc, *Px;
    int* cnt;
    cudaGetSymbolAddress((void**)&agg, g_agg);
    cudaGetSymbolAddress((void**)&inv, g_inv);
    cudaGetSymbolAddress((void**)&cnt, g_cnt);
    cudaGetSymbolAddress((void**)&Wc,  g_Wc);
    cudaGetSymbolAddress((void**)&Px,  g_Px);

    cudaFuncSetAttribute(edge_mma, cudaFuncAttributeMaxDynamicSharedMemorySize, E_SMEM);
    cudaFuncSetAttribute(node_mma, cudaFuncAttributeMaxDynamicSharedMemorySize, SMEMSZ);
    cudaFuncSetAttribute(px_k,     cudaFuncAttributeMaxDynamicSharedMemorySize, SMEMSZ);

    int smcount = 148;
    cudaDeviceGetAttribute(&smcount, cudaDevAttrMultiProcessorCount, 0);
    int ge = 2 * smcount < ET ? 2 * smcount : ET;
    int gn = smcount < NT ? smcount : NT;

    // Edge kernel is my 4th launch (global #6 with harness prelaunches; -s 5 window).
    prolog_k<<<(NN * DD / 4 + 255) / 256, 256>>>(eidx, agg, cnt);        // 0
    combine_w_k<<<(128 * 128 + 255) / 256, 256>>>(We1, Wc);              // 1
    px_k<<<gn, 256, SMEMSZ>>>(x, Wc, be1, Px);                           // 2
    edge_mma<<<ge, 256, E_SMEM>>>(ea, eidx, Px, Wc, We2, be2,            // 3 <- profiled
                                  out_ea, agg, ET);
    count_k<<<(EE + 255) / 256, 256>>>(eidx, cnt);                       // 4
    inv_k<<<(NN + 255) / 256, 256>>>(cnt, inv);                          // 5
    node_mma<<<gn, 256, SMEMSZ>>>(x, agg, Wn1, bn1, Wn2, bn2,            // 6
                                  out_x, inv, NN);

    // iteration 2
    zero_f4<<<(NN * DD / 4 + 255) / 256, 256>>>(agg, NN * DD / 4);
    px_k<<<gn, 256, SMEMSZ>>>(out_x, Wc, be1, Px);
    edge_mma<<<ge, 256, E_SMEM>>>(out_ea, eidx, Px, Wc, We2, be2,
                                  out_ea, agg, ET);
    node_mma<<<gn, 256, SMEMSZ>>>(out_x, agg, Wn1, bn1, Wn2, bn2,
                                  out_x, inv, NN);
}

// round 12
// speedup vs baseline: 1.1982x; 1.0500x over previous
#include <cuda_runtime.h>
#include <cuda_bf16.h>
#include <cstdint>

#define NN 50000
#define EE 800000
#define DD 64
#define ET 6250                 // EE / 128
#define NT 391                  // ceil(NN / 128)
#define KP 136                  // node-kernel padded K stride (bf16)

// ---------------- device-global scratch (no allocations allowed) ----------
__device__ float g_agg[NN * DD];
__device__ float g_agg2[NN * DD];
__device__ float g_inv[NN];
__device__ int   g_cnt[NN];
__device__ float g_Wc[128 * 128];
__device__ float g_Px[NN * 128];   // per-node x @ Wc[0:64] + be1
__device__ int   g_is64;

__device__ __forceinline__ int load_row(const void* eidx, int i) {
    if (g_is64) return (int)((const long long*)eidx)[i];
    return ((const int*)eidx)[i];
}

// Prologue: zero BOTH agg buffers + cnt, detect eidx dtype.
__global__ void prolog_k(const void* eidx, float* agg1, float* agg2, int* cnt) {
    int i = blockIdx.x * blockDim.x + threadIdx.x;
    if (i < NN * DD / 4) {
        ((float4*)agg1)[i] = make_float4(0.f, 0.f, 0.f, 0.f);
        ((float4*)agg2)[i] = make_float4(0.f, 0.f, 0.f, 0.f);
    }
    if (i < NN) cnt[i] = 0;
    if (i == 0) {
        const long long* p = (const long long*)eidx;
        int ok = 1;
        for (int j = 0; j < 64; j++) {
            long long v = p[j];
            if (v < 0 || v >= NN) { ok = 0; break; }
        }
        g_is64 = ok;
    }
}

// Combine We1 halves + per-node edge count (cnt zeroed by prolog).
__global__ void combine_count_k(const float* __restrict__ We1, float* __restrict__ Wc,
                                const void* __restrict__ eidx, int* cnt) {
    int i = blockIdx.x * blockDim.x + threadIdx.x;
    if (i < 128 * 128) {
        int k = i >> 7, n = i & 127;
        float v = We1[(k + 64) * 128 + n];
        if (k < 64) v += We1[k * 128 + n];
        Wc[i] = v;
    }
    if (i < EE) atomicAdd(&cnt[load_row(eidx, i)], 1);
}

__global__ void inv_k(const int* __restrict__ cnt, float* __restrict__ inv) {
    int i = blockIdx.x * blockDim.x + threadIdx.x;
    if (i < NN) inv[i] = 1.0f / fmaxf((float)cnt[i], 1.0f);
}

// ---------------- helpers ---------------------------------------------------
// Fast bf16 split-2: packed cvt.rn.bf16x2.f32 (sm_80+ PTX).
__device__ __forceinline__ void split_pair(float f0, float f1, uint32_t& hi, uint32_t& lo) {
    asm("cvt.rn.bf16x2.f32 %0, %1, %2;" : "=r"(hi) : "f"(f1), "f"(f0));
    float h0 = __uint_as_float(hi << 16);
    float h1 = __uint_as_float(hi & 0xFFFF0000u);
    float r0 = f0 - h0;
    float r1 = f1 - h1;
    asm("cvt.rn.bf16x2.f32 %0, %1, %2;" : "=r"(lo) : "f"(r1), "f"(r0));
}

// m16n8k16 row.col bf16 -> f32 accumulate (baseline PTX, sm_80+)
__device__ __forceinline__ void mma_bf16(float* d, const uint32_t* a, const uint32_t* b) {
    asm volatile(
        "mma.sync.aligned.m16n8k16.row.col.f32.bf16.bf16.f32 "
        "{%0,%1,%2,%3}, {%4,%5,%6,%7}, {%8,%9}, {%0,%1,%2,%3};"
        : "+f"(d[0]), "+f"(d[1]), "+f"(d[2]), "+f"(d[3])
        : "r"(a[0]), "r"(a[1]), "r"(a[2]), "r"(a[3]), "r"(b[0]), "r"(b[1]));
}

// ================= EDGE KERNEL: ks-planar affine layouts ===================
// Block (16B) at [plane ks][row][qt]: {hi(k2,k2+1), hi(k2+8,k2+9),
// lo(k2,k2+1), lo(k2+8,k2+9)}, k2 = 16ks+2qt. Read addresses are
// base(g,qt) + literal(nt,ks): zero per-load ALU; phase slot = (4g+qt) mod 8
// -> conflict-free reads with NO padding. Raw/D2 staging keeps the XOR layout
// (conflict-free both directions).
#define E_SA   0                  // 32KB: raw ea -> blocked A (planar) -> D2
#define E_SW1  32768              // W1: 4 planes x 128 rows x 64B
#define E_SW2  65536              // W2: 8 planes x 64 rows x 64B
#define E_B2   98304              // 64 f32
#define E_RW   98560              // 128 int rows
#define E_SMEM 99072

__global__ void __launch_bounds__(256, 2)
edge_mma(const float* __restrict__ ea, const void* __restrict__ eidx,
         const float* __restrict__ Px,
         const float* __restrict__ Wc, const float* __restrict__ W2,
         const float* __restrict__ b2,
         float* __restrict__ dst, float* __restrict__ agg, int ntiles)
{
    extern __shared__ char smc[];
    float* sb2  = (float*)(smc + E_B2);
    int*   sRows = (int*)(smc + E_RW);

    const int tid = threadIdx.x;
    const int lane = tid & 31, w = tid >> 5;
    const int g = lane >> 2, qt = lane & 3;
    const int mrow0 = 16 * w + g;

    // ---- stage W1 = Wc rows 64:127 (K=64) into planes 0..3 ----
    {
        const int n = tid & 127, h = tid >> 7;
        uint32_t hi[16], lo[16];
        #pragma unroll
        for (int p = 0; p < 16; p++) {
            int k = 32 * h + 2 * p;
            split_pair(Wc[(64 + k) * 128 + n], Wc[(64 + k + 1) * 128 + n], hi[p], lo[p]);
        }
        #pragma unroll
        for (int ksl = 0; ksl < 2; ksl++)
            #pragma unroll
            for (int q = 0; q < 4; q++) {
                uint4 blk = make_uint4(hi[8 * ksl + q], hi[8 * ksl + q + 4],
                                       lo[8 * ksl + q], lo[8 * ksl + q + 4]);
                *(uint4*)(smc + E_SW1 + (2 * h + ksl) * 8192 + n * 64 + q * 16) = blk;
            }
    }
    // ---- stage W2 (64n x K=128) into planes 0..7 ----
    {
        const int n = tid & 63, kq = tid >> 6;
        uint32_t hi[16], lo[16];
        #pragma unroll
        for (int p = 0; p < 16; p++) {
            int k = 32 * kq + 2 * p;
            split_pair(W2[k * 64 + n], W2[(k + 1) * 64 + n], hi[p], lo[p]);
        }
        #pragma unroll
        for (int ksl = 0; ksl < 2; ksl++)
            #pragma unroll
            for (int q = 0; q < 4; q++) {
                uint4 blk = make_uint4(hi[8 * ksl + q], hi[8 * ksl + q + 4],
                                       lo[8 * ksl + q], lo[8 * ksl + q + 4]);
                *(uint4*)(smc + E_SW2 + (2 * kq + ksl) * 4096 + n * 64 + q * 16) = blk;
            }
    }
    if (tid < 64) sb2[tid] = b2[tid];
    __syncthreads();

    // kernel-constant base pointers: all GEMM loads are [base + literal]
    const char* pA  = smc + E_SA  + mrow0 * 64 + qt * 16;
    const char* pB1 = smc + E_SW1 + g * 64 + qt * 16;
    const char* pB2 = smc + E_SW2 + g * 64 + qt * 16;
    const int m = tid & 127, h = tid >> 7;
    const char* praw = smc + E_SA + m * 256;
    const int mx = m & 15;

    for (int tile = blockIdx.x; tile < ntiles; tile += gridDim.x) {
        const int i0 = tile * 128;

        if (tid < 128) sRows[tid] = load_row(eidx, i0 + tid);
        const int r0 = load_row(eidx, i0 + mrow0);
        const int r1 = load_row(eidx, i0 + mrow0 + 8);

        // ---- phase 1: coalesced raw copy of ea tile (XOR chunk layout) ----
        {
            const uint4* src = (const uint4*)(ea + (size_t)i0 * DD);
            #pragma unroll
            for (int p = 0; p < 8; p++) {
                int id = p * 256 + tid;
                int row = id >> 4, c = id & 15;
                *(uint4*)(smc + E_SA + (row << 8) + (((c ^ (row & 15)) & 15) << 4)) = src[id];
            }
        }
        __syncthreads();

        // ---- phase 2: read own half-row from raw (conflict-free) ----
        uint4 raw[8];
        #pragma unroll
        for (int j = 0; j < 8; j++)
            raw[j] = *(const uint4*)(praw + ((((8 * h + j) ^ mx) & 15) << 4));
        __syncthreads();

        // ---- phase 3: convert + planar blocked STS ----
        {
            uint32_t hiP[8][2], loP[8][2];
            #pragma unroll
            for (int j = 0; j < 8; j++) {
                float f0 = __uint_as_float(raw[j].x);
                float f1 = __uint_as_float(raw[j].y);
                float f2 = __uint_as_float(raw[j].z);
                float f3 = __uint_as_float(raw[j].w);
                split_pair(f0, f1, hiP[j][0], loP[j][0]);
                split_pair(f2, f3, hiP[j][1], loP[j][1]);
            }
            #pragma unroll
            for (int ksl = 0; ksl < 2; ksl++)
                #pragma unroll
                for (int q = 0; q < 4; q++) {
                    int j = 4 * ksl + (q >> 1), e = q & 1;
                    uint4 blk = make_uint4(hiP[j][e], hiP[j + 2][e],
                                           loP[j][e], loP[j + 2][e]);
                    *(uint4*)(smc + E_SA + (2 * h + ksl) * 8192 + m * 64 + q * 16) = blk;
                }
        }

        // ---- init acc1 from Px gather (be1 folded into Px) ----
        float acc1[16][4];
        {
            const float* pr0 = Px + (size_t)r0 * 128 + 2 * qt;
            const float* pr1 = Px + (size_t)r1 * 128 + 2 * qt;
            #pragma unroll
            for (int nt = 0; nt < 16; nt++) {
                float2 v0 = *(const float2*)(pr0 + 8 * nt);
                float2 v1 = *(const float2*)(pr1 + 8 * nt);
                acc1[nt][0] = v0.x; acc1[nt][1] = v0.y;
                acc1[nt][2] = v1.x; acc1[nt][3] = v1.y;
            }
        }
        __syncthreads();

        // ---- GEMM1: acc1 += ea @ W1 (K=64, 3 split terms), literal offsets
        #pragma unroll
        for (int ks = 0; ks < 4; ks++) {
            uint4 A0 = *(const uint4*)(pA + ks * 8192);
            uint4 A1 = *(const uint4*)(pA + ks * 8192 + 512);
            uint32_t ah[4] = {A0.x, A1.x, A0.y, A1.y};
            uint32_t al[4] = {A0.z, A1.z, A0.w, A1.w};
            #pragma unroll
            for (int nt = 0; nt < 16; nt++) {
                uint4 B = *(const uint4*)(pB1 + ks * 8192 + nt * 512);
                uint32_t bh[2] = {B.x, B.y}, bl[2] = {B.z, B.w};
                mma_bf16(acc1[nt], ah, bh);
                mma_bf16(acc1[nt], ah, bl);
                mma_bf16(acc1[nt], al, bh);
            }
        }
        __syncthreads();   // sA reads done -> reusable for D2 staging

        // ---- pack H fragments (relu fused); acc1 dies here ----
        uint32_t hA[8][4], lA[8][4];
        #pragma unroll
        for (int ks = 0; ks < 8; ks++) {
            float v00 = fmaxf(acc1[2 * ks][0], 0.f);
            float v01 = fmaxf(acc1[2 * ks][1], 0.f);
            float v02 = fmaxf(acc1[2 * ks][2], 0.f);
            float v03 = fmaxf(acc1[2 * ks][3], 0.f);
            float v10 = fmaxf(acc1[2 * ks + 1][0], 0.f);
            float v11 = fmaxf(acc1[2 * ks + 1][1], 0.f);
            float v12 = fmaxf(acc1[2 * ks + 1][2], 0.f);
            float v13 = fmaxf(acc1[2 * ks + 1][3], 0.f);
            split_pair(v00, v01, hA[ks][0], lA[ks][0]);
            split_pair(v02, v03, hA[ks][1], lA[ks][1]);
            split_pair(v10, v11, hA[ks][2], lA[ks][2]);
            split_pair(v12, v13, hA[ks][3], lA[ks][3]);
        }

        // ---- GEMM2: acc2 = H @ W2 (K=128), literal offsets ----
        float acc2[8][4];
        #pragma unroll
        for (int nt = 0; nt < 8; nt++)
            #pragma unroll
            for (int j = 0; j < 4; j++) acc2[nt][j] = 0.f;

        #pragma unroll
        for (int ks = 0; ks < 8; ks++) {
            #pragma unroll
            for (int nt = 0; nt < 8; nt++) {
                uint4 B = *(const uint4*)(pB2 + ks * 4096 + nt * 512);
                uint32_t bh[2] = {B.x, B.y}, bl[2] = {B.z, B.w};
                mma_bf16(acc2[nt], hA[ks], bh);
                mma_bf16(acc2[nt], hA[ks], bl);
                mma_bf16(acc2[nt], lA[ks], bh);
            }
        }

        // ---- stage D2 into sA (XOR chunk layout, natural slot order) ----
        #pragma unroll
        for (int nt = 0; nt < 8; nt++) {
            int c = 2 * nt + (qt >> 1), s = qt & 1;
            {
                int r = mrow0;
                uint32_t a = (uint32_t)(r << 8) + ((uint32_t)((c ^ (r & 15)) & 15) << 4)
                           + ((uint32_t)s << 3);
                *(float2*)(smc + E_SA + a) = make_float2(acc2[nt][0], acc2[nt][1]);
            }
            {
                int r = mrow0 + 8;
                uint32_t a = (uint32_t)(r << 8) + ((uint32_t)((c ^ (r & 15)) & 15) << 4)
                           + ((uint32_t)s << 3);
                *(float2*)(smc + E_SA + a) = make_float2(acc2[nt][2], acc2[nt][3]);
            }
        }
        __syncthreads();

        // ---- coalesced epilogue: red.v4 agg; dst = ea + (D2 + b2) ----
        {
            const float4* easrc = (const float4*)(ea + (size_t)i0 * DD);
            float4* dstp = (float4*)(dst + (size_t)i0 * DD);
            #pragma unroll
            for (int p = 0; p < 8; p++) {
                int id = p * 256 + tid;
                int row = id >> 4, c = id & 15;
                uint4 d = *(const uint4*)(smc + E_SA + (row << 8)
                                          + (((c ^ (row & 15)) & 15) << 4));
                float4 v;
                v.x = __uint_as_float(d.x) + sb2[4 * c + 0];
                v.y = __uint_as_float(d.y) + sb2[4 * c + 1];
                v.z = __uint_as_float(d.z) + sb2[4 * c + 2];
                v.w = __uint_as_float(d.w) + sb2[4 * c + 3];
                float* ap = agg + (size_t)sRows[row] * DD + 4 * c;
                asm volatile("red.global.add.v4.f32 [%0], {%1, %2, %3, %4};"
                             :: "l"(ap), "f"(v.x), "f"(v.y), "f"(v.z), "f"(v.w)
                             : "memory");
                float4 e = easrc[id];
                float4 o = make_float4(e.x + v.x, e.y + v.y, e.z + v.z, e.w + v.w);
                dstp[id] = o;
            }
        }
        __syncthreads();   // D2 reads done before next tile's raw copy
    }
}

// ---------------- node / px kernels (round-11, known good) -----------------
#define OFF_AH   0
#define OFF_AL   34816
#define OFF_W1H  69632
#define OFF_W1L  104448
#define OFF_W2H  139264
#define OFF_W2L  156672
#define OFF_B1   174080
#define OFF_B2   174592
#define SMEMSZ   175360

__global__ void __launch_bounds__(256, 1)
px_k(const float* __restrict__ x, const float* __restrict__ Wc,
     const float* __restrict__ be1, float* __restrict__ Px)
{
    extern __shared__ char smc[];
    uint16_t* sAh = (uint16_t*)(smc + OFF_AH);
    uint16_t* sAl = (uint16_t*)(smc + OFF_AL);
    uint16_t* sWh = (uint16_t*)(smc + OFF_W1H);
    uint16_t* sWl = (uint16_t*)(smc + OFF_W1L);
    float*    sb1 = (float*)(smc + OFF_B1);

    const int tid = threadIdx.x;
    const int lane = tid & 31, w = tid >> 5;
    const int g = lane >> 2, qt = lane & 3;
    const int wm = w >> 1, wn = w & 1;

    {
        int n = tid & 127, k0 = (tid >> 7) * 32;
        for (int k = k0; k < k0 + 32; k += 2) {
            uint32_t hi, lo;
            split_pair(Wc[k * 128 + n], Wc[(k + 1) * 128 + n], hi, lo);
            *(uint32_t*)&sWh[n * KP + k] = hi;
            *(uint32_t*)&sWl[n * KP + k] = lo;
        }
    }
    if (tid < 128) sb1[tid] = be1[tid];
    __syncthreads();

    for (int tile = blockIdx.x; tile < NT; tile += gridDim.x) {
        const int i0 = tile * 128;
        {
            const int m = tid & 127, ch = (tid >> 7) * 32;
            const int gi = i0 + m;
            const bool valid = gi < NN;
            const float* src = x + (size_t)(valid ? gi : 0) * DD + ch;
            #pragma unroll
            for (int c = 0; c < 32; c += 8) {
                float4 f0, f1;
                if (valid) { f0 = *(const float4*)(src + c); f1 = *(const float4*)(src + c + 4); }
                else { f0 = make_float4(0,0,0,0); f1 = f0; }
                uint32_t hw[4], lw[4];
                split_pair(f0.x, f0.y, hw[0], lw[0]);
                split_pair(f0.z, f0.w, hw[1], lw[1]);
                split_pair(f1.x, f1.y, hw[2], lw[2]);
                split_pair(f1.z, f1.w, hw[3], lw[3]);
                int e = m * KP + ch + c;
                *(uint4*)&sAh[e] = *(uint4*)hw;
                *(uint4*)&sAl[e] = *(uint4*)lw;
            }
        }
        __syncthreads();

        float acc[2][8][4];
        #pragma unroll
        for (int mt = 0; mt < 2; mt++)
            #pragma unroll
            for (int nt = 0; nt < 8; nt++)
                #pragma unroll
                for (int j = 0; j < 4; j++) acc[mt][nt][j] = 0.f;

        #pragma unroll
        for (int ks = 0; ks < 4; ks++) {
            const int kb = ks * 16 + 2 * qt;
            uint32_t ah[2][4], al[2][4];
            #pragma unroll
            for (int mt = 0; mt < 2; mt++) {
                int e = (wm * 32 + mt * 16 + g) * KP + kb;
                ah[mt][0] = *(const uint32_t*)&sAh[e];
                ah[mt][1] = *(const uint32_t*)&sAh[e + 8 * KP];
                ah[mt][2] = *(const uint32_t*)&sAh[e + 8];
                ah[mt][3] = *(const uint32_t*)&sAh[e + 8 * KP + 8];
                al[mt][0] = *(const uint32_t*)&sAl[e];
                al[mt][1] = *(const uint32_t*)&sAl[e + 8 * KP];
                al[mt][2] = *(const uint32_t*)&sAl[e + 8];
                al[mt][3] = *(const uint32_t*)&sAl[e + 8 * KP + 8];
            }
            #pragma unroll
            for (int nt = 0; nt < 8; nt++) {
                int e = (wn * 64 + nt * 8 + g) * KP + kb;
                uint32_t bh[2], bl[2];
                bh[0] = *(const uint32_t*)&sWh[e];
                bh[1] = *(const uint32_t*)&sWh[e + 8];
                bl[0] = *(const uint32_t*)&sWl[e];
                bl[1] = *(const uint32_t*)&sWl[e + 8];
                mma_bf16(acc[0][nt], ah[0], bh);
                mma_bf16(acc[1][nt], ah[1], bh);
                mma_bf16(acc[0][nt], ah[0], bl);
                mma_bf16(acc[1][nt], ah[1], bl);
                mma_bf16(acc[0][nt], al[0], bh);
                mma_bf16(acc[1][nt], al[1], bh);
            }
        }

        #pragma unroll
        for (int mt = 0; mt < 2; mt++)
            #pragma unroll
            for (int nt = 0; nt < 8; nt++) {
                int rl = wm * 32 + mt * 16 + g;
                int col = wn * 64 + nt * 8 + 2 * qt;
                #pragma unroll
                for (int rh = 0; rh < 2; rh++) {
                    int gi = i0 + rl + rh * 8;
                    if (gi >= NN) continue;
                    float2 v = make_float2(acc[mt][nt][rh * 2] + sb1[col],
                                           acc[mt][nt][rh * 2 + 1] + sb1[col + 1]);
                    *(float2*)&Px[(size_t)gi * 128 + col] = v;
                }
            }
        __syncthreads();
    }
}

__global__ void __launch_bounds__(256, 1)
node_mma(const float* __restrict__ x_src, const float* __restrict__ a_src,
         const float* __restrict__ W1, const float* __restrict__ b1,
         const float* __restrict__ W2, const float* __restrict__ b2,
         float* __restrict__ dst, const float* __restrict__ inv, int count)
{
    extern __shared__ char smc[];
    uint16_t* sAh  = (uint16_t*)(smc + OFF_AH);
    uint16_t* sAl  = (uint16_t*)(smc + OFF_AL);
    uint16_t* sW1h = (uint16_t*)(smc + OFF_W1H);
    uint16_t* sW1l = (uint16_t*)(smc + OFF_W1L);
    uint16_t* sW2h = (uint16_t*)(smc + OFF_W2H);
    uint16_t* sW2l = (uint16_t*)(smc + OFF_W2L);
    float*    sb1  = (float*)(smc + OFF_B1);
    float*    sb2  = (float*)(smc + OFF_B2);

    const int tid = threadIdx.x;
    const int lane = tid & 31, w = tid >> 5;
    const int g = lane >> 2, qt = lane & 3;
    const int wm = w >> 1, wn = w & 1;

    {
        int n = tid & 127, k0 = (tid >> 7) * 64;
        for (int k = k0; k < k0 + 64; k += 2) {
            uint32_t hi, lo;
            split_pair(W1[k * 128 + n], W1[(k + 1) * 128 + n], hi, lo);
            *(uint32_t*)&sW1h[n * KP + k] = hi;
            *(uint32_t*)&sW1l[n * KP + k] = lo;
        }
    }
    {
        int n = tid & 63, k0 = (tid >> 6) * 32;
        for (int k = k0; k < k0 + 32; k += 2) {
            uint32_t hi, lo;
            split_pair(W2[k * 64 + n], W2[(k + 1) * 64 + n], hi, lo);
            *(uint32_t*)&sW2h[n * KP + k] = hi;
            *(uint32_t*)&sW2l[n * KP + k] = lo;
        }
    }
    if (tid < 128) sb1[tid] = b1[tid];
    if (tid < 64)  sb2[tid] = b2[tid];
    __syncthreads();

    for (int tile = blockIdx.x; tile < NT; tile += gridDim.x) {
        const int i0 = tile * 128;
        {
            const int m = tid & 127, half = tid >> 7;
            const int gi = i0 + m;
            const bool valid = gi < count;
            const float* src;
            float scale = 1.0f;
            bool doscale = false;
            if (half == 0) {
                src = x_src + (size_t)(valid ? gi : 0) * DD;
            } else {
                src = a_src + (size_t)(valid ? gi : 0) * DD;
                scale = valid ? inv[gi] : 0.0f;
                doscale = true;
            }
            #pragma unroll
            for (int c = 0; c < 64; c += 8) {
                float4 f0 = *(const float4*)(src + c);
                float4 f1 = *(const float4*)(src + c + 4);
                if (doscale) {
                    f0.x *= scale; f0.y *= scale; f0.z *= scale; f0.w *= scale;
                    f1.x *= scale; f1.y *= scale; f1.z *= scale; f1.w *= scale;
                }
                uint32_t hw[4], lw[4];
                split_pair(f0.x, f0.y, hw[0], lw[0]);
                split_pair(f0.z, f0.w, hw[1], lw[1]);
                split_pair(f1.x, f1.y, hw[2], lw[2]);
                split_pair(f1.z, f1.w, hw[3], lw[3]);
                int e = m * KP + half * 64 + c;
                *(uint4*)&sAh[e] = *(uint4*)hw;
                *(uint4*)&sAl[e] = *(uint4*)lw;
            }
        }
        __syncthreads();

        float acc[2][8][4];
        #pragma unroll
        for (int mt = 0; mt < 2; mt++)
            #pragma unroll
            for (int nt = 0; nt < 8; nt++)
                #pragma unroll
                for (int j = 0; j < 4; j++) acc[mt][nt][j] = 0.f;

        #pragma unroll
        for (int ks = 0; ks < 8; ks++) {
            const int kb = ks * 16 + 2 * qt;
            uint32_t ah[2][4], al[2][4];
            #pragma unroll
            for (int mt = 0; mt < 2; mt++) {
                int e = (wm * 32 + mt * 16 + g) * KP + kb;
                ah[mt][0] = *(const uint32_t*)&sAh[e];
                ah[mt][1] = *(const uint32_t*)&sAh[e + 8 * KP];
                ah[mt][2] = *(const uint32_t*)&sAh[e + 8];
                ah[mt][3] = *(const uint32_t*)&sAh[e + 8 * KP + 8];
                al[mt][0] = *(const uint32_t*)&sAl[e];
                al[mt][1] = *(const uint32_t*)&sAl[e + 8 * KP];
                al[mt][2] = *(const uint32_t*)&sAl[e + 8];
                al[mt][3] = *(const uint32_t*)&sAl[e + 8 * KP + 8];
            }
            #pragma unroll
            for (int nt = 0; nt < 8; nt++) {
                int e = (wn * 64 + nt * 8 + g) * KP + kb;
                uint32_t bh[2], bl[2];
                bh[0] = *(const uint32_t*)&sW1h[e];
                bh[1] = *(const uint32_t*)&sW1h[e + 8];
                bl[0] = *(const uint32_t*)&sW1l[e];
                bl[1] = *(const uint32_t*)&sW1l[e + 8];
                mma_bf16(acc[0][nt], ah[0], bh);
                mma_bf16(acc[1][nt], ah[1], bh);
                mma_bf16(acc[0][nt], ah[0], bl);
                mma_bf16(acc[1][nt], ah[1], bl);
                mma_bf16(acc[0][nt], al[0], bh);
                mma_bf16(acc[1][nt], al[1], bh);
            }
        }
        __syncthreads();

        #pragma unroll
        for (int mt = 0; mt < 2; mt++)
            #pragma unroll
            for (int nt = 0; nt < 8; nt++) {
                int row = wm * 32 + mt * 16 + g;
                int col = wn * 64 + nt * 8 + 2 * qt;
                float v0 = fmaxf(acc[mt][nt][0] + sb1[col], 0.f);
                float v1 = fmaxf(acc[mt][nt][1] + sb1[col + 1], 0.f);
                float v2 = fmaxf(acc[mt][nt][2] + sb1[col], 0.f);
                float v3 = fmaxf(acc[mt][nt][3] + sb1[col + 1], 0.f);
                uint32_t hi, lo;
                split_pair(v0, v1, hi, lo);
                *(uint32_t*)&sAh[row * KP + col] = hi;
                *(uint32_t*)&sAl[row * KP + col] = lo;
                split_pair(v2, v3, hi, lo);
                *(uint32_t*)&sAh[(row + 8) * KP + col] = hi;
                *(uint32_t*)&sAl[(row + 8) * KP + col] = lo;
            }
        __syncthreads();

        float acc2[2][4][4];
        #pragma unroll
        for (int mt = 0; mt < 2; mt++)
            #pragma unroll
            for (int nt = 0; nt < 4; nt++)
                #pragma unroll
                for (int j = 0; j < 4; j++) acc2[mt][nt][j] = 0.f;

        #pragma unroll
        for (int ks = 0; ks < 8; ks++) {
            const int kb = ks * 16 + 2 * qt;
            uint32_t ah[2][4], al[2][4];
            #pragma unroll
            for (int mt = 0; mt < 2; mt++) {
                int e = (wm * 32 + mt * 16 + g) * KP + kb;
                ah[mt][0] = *(const uint32_t*)&sAh[e];
                ah[mt][1] = *(const uint32_t*)&sAh[e + 8 * KP];
                ah[mt][2] = *(const uint32_t*)&sAh[e + 8];
                ah[mt][3] = *(const uint32_t*)&sAh[e + 8 * KP + 8];
                al[mt][0] = *(const uint32_t*)&sAl[e];
                al[mt][1] = *(const uint32_t*)&sAl[e + 8 * KP];
                al[mt][2] = *(const uint32_t*)&sAl[e + 8];
                al[mt][3] = *(const uint32_t*)&sAl[e + 8 * KP + 8];
            }
            #pragma unroll
            for (int nt = 0; nt < 4; nt++) {
                int e = (wn * 32 + nt * 8 + g) * KP + kb;
                uint32_t bh[2], bl[2];
                bh[0] = *(const uint32_t*)&sW2h[e];
                bh[1] = *(const uint32_t*)&sW2h[e + 8];
                bl[0] = *(const uint32_t*)&sW2l[e];
                bl[1] = *(const uint32_t*)&sW2l[e + 8];
                mma_bf16(acc2[0][nt], ah[0], bh);
                mma_bf16(acc2[1][nt], ah[1], bh);
                mma_bf16(acc2[0][nt], ah[0], bl);
                mma_bf16(acc2[1][nt], ah[1], bl);
                mma_bf16(acc2[0][nt], al[0], bh);
                mma_bf16(acc2[1][nt], al[1], bh);
            }
        }

        #pragma unroll
        for (int mt = 0; mt < 2; mt++)
            #pragma unroll
            for (int nt = 0; nt < 4; nt++) {
                int rl = wm * 32 + mt * 16 + g;
                int col = wn * 32 + nt * 8 + 2 * qt;
                #pragma unroll
                for (int rh = 0; rh < 2; rh++) {
                    int row = rl + rh * 8;
                    int gi = i0 + row;
                    if (gi >= count) continue;
                    float vx = acc2[mt][nt][rh * 2 + 0] + sb2[col];
                    float vy = acc2[mt][nt][rh * 2 + 1] + sb2[col + 1];
                    float2 rv = *(const float2*)(x_src + (size_t)gi * DD + col);
                    *(float2*)(dst + (size_t)gi * DD + col) =
                        make_float2(rv.x + vx, rv.y + vy);
                }
            }
        __syncthreads();
    }
}

extern "C" void kernel_launch(void* const* d_in, const int* in_sizes, int n_in,
                              void* d_out, int out_size)
{
    const float* x   = (const float*)d_in[0];
    const float* ea  = (const float*)d_in[1];
    const float* We1 = (const float*)d_in[2];
    const float* be1 = (const float*)d_in[3];
    const float* We2 = (const float*)d_in[4];
    const float* be2 = (const float*)d_in[5];
    const float* Wn1 = (const float*)d_in[6];
    const float* bn1 = (const float*)d_in[7];
    const float* Wn2 = (const float*)d_in[8];
    const float* bn2 = (const float*)d_in[9];
    const void*  eidx = d_in[10];

    float* out_x  = (float*)d_out;
    float* out_ea = (float*)d_out + (size_t)NN * DD;

    float *agg, *agg2, *inv, *Wc, *Px;
    int* cnt;
    cudaGetSymbolAddress((void**)&agg,  g_agg);
    cudaGetSymbolAddress((void**)&agg2, g_agg2);
    cudaGetSymbolAddress((void**)&inv,  g_inv);
    cudaGetSymbolAddress((void**)&cnt,  g_cnt);
    cudaGetSymbolAddress((void**)&Wc,   g_Wc);
    cudaGetSymbolAddress((void**)&Px,   g_Px);

    cudaFuncSetAttribute(edge_mma, cudaFuncAttributeMaxDynamicSharedMemorySize, E_SMEM);
    cudaFuncSetAttribute(node_mma, cudaFuncAttributeMaxDynamicSharedMemorySize, SMEMSZ);
    cudaFuncSetAttribute(px_k,     cudaFuncAttributeMaxDynamicSharedMemorySize, SMEMSZ);

    int smcount = 148;
    cudaDeviceGetAttribute(&smcount, cudaDevAttrMultiProcessorCount, 0);
    int ge = 2 * smcount < ET ? 2 * smcount : ET;
    int gn = smcount < NT ? smcount : NT;

    // Edge kernel stays at my launch index 3 (profiled by ncu -s 5 -c 1).
    prolog_k<<<(NN * DD / 4 + 255) / 256, 256>>>(eidx, agg, agg2, cnt);      // 0
    combine_count_k<<<(EE + 255) / 256, 256>>>(We1, Wc, eidx, cnt);          // 1
    px_k<<<gn, 256, SMEMSZ>>>(x, Wc, be1, Px);                               // 2
    edge_mma<<<ge, 256, E_SMEM>>>(ea, eidx, Px, Wc, We2, be2,                // 3 <- profiled
                                  out_ea, agg, ET);
    inv_k<<<(NN + 255) / 256, 256>>>(cnt, inv);                              // 4
    node_mma<<<gn, 256, SMEMSZ>>>(x, agg, Wn1, bn1, Wn2, bn2,                // 5
                                  out_x, inv, NN);

    // iteration 2 (agg2 pre-zeroed in prolog -> no mid-stream zero pass)
    px_k<<<gn, 256, SMEMSZ>>>(out_x, Wc, be1, Px);                           // 6
    edge_mma<<<ge, 256, E_SMEM>>>(out_ea, eidx, Px, Wc, We2, be2,            // 7
                                  out_ea, agg2, ET);
    node_mma<<<gn, 256, SMEMSZ>>>(out_x, agg2, Wn1, bn1, Wn2, bn2,           // 8
                                  out_x, inv, NN);
}

// round 13
// speedup vs baseline: 1.2629x; 1.0540x over previous
#include <cuda_runtime.h>
#include <cuda_bf16.h>
#include <cstdint>

#define NN 50000
#define EE 800000
#define DD 64
#define ET 6250                 // EE / 128
#define NT 391                  // ceil(NN / 128)
#define KP 136                  // node-kernel padded K stride (bf16)

// ---------------- device-global scratch (no allocations allowed) ----------
__device__ float g_agg[NN * DD];
__device__ float g_agg2[NN * DD];
__device__ float g_inv[NN];
__device__ int   g_cnt[NN];
__device__ float g_Wc[128 * 128];
__device__ float g_Px[NN * 128];   // per-node x @ Wc[0:64] + be1
__device__ int   g_is64;

__device__ __forceinline__ int load_row(const void* eidx, int i) {
    if (g_is64) return (int)((const long long*)eidx)[i];
    return ((const int*)eidx)[i];
}

// Prologue: zero BOTH agg buffers + cnt, detect eidx dtype.
__global__ void prolog_k(const void* eidx, float* agg1, float* agg2, int* cnt) {
    int i = blockIdx.x * blockDim.x + threadIdx.x;
    if (i < NN * DD / 4) {
        ((float4*)agg1)[i] = make_float4(0.f, 0.f, 0.f, 0.f);
        ((float4*)agg2)[i] = make_float4(0.f, 0.f, 0.f, 0.f);
    }
    if (i < NN) cnt[i] = 0;
    if (i == 0) {
        const long long* p = (const long long*)eidx;
        int ok = 1;
        for (int j = 0; j < 64; j++) {
            long long v = p[j];
            if (v < 0 || v >= NN) { ok = 0; break; }
        }
        g_is64 = ok;
    }
}

// Combine We1 halves + per-node edge count (cnt zeroed by prolog).
__global__ void combine_count_k(const float* __restrict__ We1, float* __restrict__ Wc,
                                const void* __restrict__ eidx, int* cnt) {
    int i = blockIdx.x * blockDim.x + threadIdx.x;
    if (i < 128 * 128) {
        int k = i >> 7, n = i & 127;
        float v = We1[(k + 64) * 128 + n];
        if (k < 64) v += We1[k * 128 + n];
        Wc[i] = v;
    }
    if (i < EE) atomicAdd(&cnt[load_row(eidx, i)], 1);
}

__global__ void inv_k(const int* __restrict__ cnt, float* __restrict__ inv) {
    int i = blockIdx.x * blockDim.x + threadIdx.x;
    if (i < NN) inv[i] = 1.0f / fmaxf((float)cnt[i], 1.0f);
}

// ---------------- helpers ---------------------------------------------------
// Fast bf16 split-2: packed cvt.rn.bf16x2.f32 (sm_80+ PTX).
__device__ __forceinline__ void split_pair(float f0, float f1, uint32_t& hi, uint32_t& lo) {
    asm("cvt.rn.bf16x2.f32 %0, %1, %2;" : "=r"(hi) : "f"(f1), "f"(f0));
    float h0 = __uint_as_float(hi << 16);
    float h1 = __uint_as_float(hi & 0xFFFF0000u);
    float r0 = f0 - h0;
    float r1 = f1 - h1;
    asm("cvt.rn.bf16x2.f32 %0, %1, %2;" : "=r"(lo) : "f"(r1), "f"(r0));
}

// m16n8k16 row.col bf16 -> f32 accumulate (baseline PTX, sm_80+)
__device__ __forceinline__ void mma_bf16(float* d, const uint32_t* a, const uint32_t* b) {
    asm volatile(
        "mma.sync.aligned.m16n8k16.row.col.f32.bf16.bf16.f32 "
        "{%0,%1,%2,%3}, {%4,%5,%6,%7}, {%8,%9}, {%0,%1,%2,%3};"
        : "+f"(d[0]), "+f"(d[1]), "+f"(d[2]), "+f"(d[3])
        : "r"(a[0]), "r"(a[1]), "r"(a[2]), "r"(a[3]), "r"(b[0]), "r"(b[1]));
}

// ================= EDGE KERNEL: fragment-direct A path =====================
// ea staged raw (coalesced, 16B-chunk XOR layout); each thread converts its
// OWN fragment float2s straight into registers (aH/aL[4][4]) -> no blocked-A
// smem, one fewer barrier. W planes are ks-planar affine (zero-ALU loads).
#define E_SA   0                  // 32KB: raw ea -> (later) D2 staging
#define E_SW1  32768              // W1: 4 planes x 128 rows x 64B
#define E_SW2  65536              // W2: 8 planes x 64 rows x 64B
#define E_B2   98304              // 64 f32
#define E_RW   98560              // 128 int rows
#define E_SMEM 99072

__global__ void __launch_bounds__(256, 2)
edge_mma(const float* __restrict__ ea, const void* __restrict__ eidx,
         const float* __restrict__ Px,
         const float* __restrict__ Wc, const float* __restrict__ W2,
         const float* __restrict__ b2,
         float* __restrict__ dst, float* __restrict__ agg, int ntiles)
{
    extern __shared__ char smc[];
    float* sb2  = (float*)(smc + E_B2);
    int*   sRows = (int*)(smc + E_RW);

    const int tid = threadIdx.x;
    const int lane = tid & 31, w = tid >> 5;
    const int g = lane >> 2, qt = lane & 3;
    const int mrow0 = 16 * w + g;

    // ---- stage W1 = Wc rows 64:127 (K=64) into planes 0..3 ----
    {
        const int n = tid & 127, h = tid >> 7;
        uint32_t hi[16], lo[16];
        #pragma unroll
        for (int p = 0; p < 16; p++) {
            int k = 32 * h + 2 * p;
            split_pair(Wc[(64 + k) * 128 + n], Wc[(64 + k + 1) * 128 + n], hi[p], lo[p]);
        }
        #pragma unroll
        for (int ksl = 0; ksl < 2; ksl++)
            #pragma unroll
            for (int q = 0; q < 4; q++) {
                uint4 blk = make_uint4(hi[8 * ksl + q], hi[8 * ksl + q + 4],
                                       lo[8 * ksl + q], lo[8 * ksl + q + 4]);
                *(uint4*)(smc + E_SW1 + (2 * h + ksl) * 8192 + n * 64 + q * 16) = blk;
            }
    }
    // ---- stage W2 (64n x K=128) into planes 0..7 ----
    {
        const int n = tid & 63, kq = tid >> 6;
        uint32_t hi[16], lo[16];
        #pragma unroll
        for (int p = 0; p < 16; p++) {
            int k = 32 * kq + 2 * p;
            split_pair(W2[k * 64 + n], W2[(k + 1) * 64 + n], hi[p], lo[p]);
        }
        #pragma unroll
        for (int ksl = 0; ksl < 2; ksl++)
            #pragma unroll
            for (int q = 0; q < 4; q++) {
                uint4 blk = make_uint4(hi[8 * ksl + q], hi[8 * ksl + q + 4],
                                       lo[8 * ksl + q], lo[8 * ksl + q + 4]);
                *(uint4*)(smc + E_SW2 + (2 * kq + ksl) * 4096 + n * 64 + q * 16) = blk;
            }
    }
    if (tid < 64) sb2[tid] = b2[tid];
    __syncthreads();

    // kernel-constant base pointers for B loads: [base + literal]
    const char* pB1 = smc + E_SW1 + g * 64 + qt * 16;
    const char* pB2 = smc + E_SW2 + g * 64 + qt * 16;
    // raw-region constants for this thread's fragment reads
    const char* praw0 = smc + E_SA + mrow0 * 256;           // row mrow0
    const char* praw1 = smc + E_SA + (mrow0 + 8) * 256;     // row mrow0+8
    const int x0 = mrow0 & 15, x1 = (mrow0 + 8) & 15;
    const int coff = qt >> 1, soff = 8 * (qt & 1);          // chunk/in-chunk

    for (int tile = blockIdx.x; tile < ntiles; tile += gridDim.x) {
        const int i0 = tile * 128;

        if (tid < 128) sRows[tid] = load_row(eidx, i0 + tid);
        const int r0 = load_row(eidx, i0 + mrow0);
        const int r1 = load_row(eidx, i0 + mrow0 + 8);

        // ---- phase 1: coalesced raw copy of ea tile (XOR chunk layout) ----
        {
            const uint4* src = (const uint4*)(ea + (size_t)i0 * DD);
            #pragma unroll
            for (int p = 0; p < 8; p++) {
                int id = p * 256 + tid;
                int row = id >> 4, c = id & 15;
                *(uint4*)(smc + E_SA + (row << 8) + (((c ^ (row & 15)) & 15) << 4)) = src[id];
            }
        }
        __syncthreads();

        // ---- phase 2: fragment-direct convert (raw -> registers) ----
        uint32_t aH[4][4], aL[4][4];
        #pragma unroll
        for (int ks = 0; ks < 4; ks++) {
            int c = 4 * ks + coff;          // k2 = 16ks+2qt -> chunk, +2 for k2+8
            float2 f0 = *(const float2*)(praw0 + (((c     ^ x0) & 15) << 4) + soff);
            float2 f1 = *(const float2*)(praw1 + (((c     ^ x1) & 15) << 4) + soff);
            float2 f2 = *(const float2*)(praw0 + ((((c+2) ^ x0) & 15) << 4) + soff);
            float2 f3 = *(const float2*)(praw1 + ((((c+2) ^ x1) & 15) << 4) + soff);
            split_pair(f0.x, f0.y, aH[ks][0], aL[ks][0]);
            split_pair(f1.x, f1.y, aH[ks][1], aL[ks][1]);
            split_pair(f2.x, f2.y, aH[ks][2], aL[ks][2]);
            split_pair(f3.x, f3.y, aH[ks][3], aL[ks][3]);
        }

        // ---- init acc1 from Px gather (be1 folded into Px) ----
        float acc1[16][4];
        {
            const float* pr0 = Px + (size_t)r0 * 128 + 2 * qt;
            const float* pr1 = Px + (size_t)r1 * 128 + 2 * qt;
            #pragma unroll
            for (int nt = 0; nt < 16; nt++) {
                float2 v0 = *(const float2*)(pr0 + 8 * nt);
                float2 v1 = *(const float2*)(pr1 + 8 * nt);
                acc1[nt][0] = v0.x; acc1[nt][1] = v0.y;
                acc1[nt][2] = v1.x; acc1[nt][3] = v1.y;
            }
        }
        __syncthreads();   // all raw reads done -> sA reusable for D2 staging

        // ---- GEMM1: acc1 += ea @ W1 (K=64, 3 split terms), A in regs ----
        #pragma unroll
        for (int ks = 0; ks < 4; ks++) {
            #pragma unroll
            for (int nt = 0; nt < 16; nt++) {
                uint4 B = *(const uint4*)(pB1 + ks * 8192 + nt * 512);
                uint32_t bh[2] = {B.x, B.y}, bl[2] = {B.z, B.w};
                mma_bf16(acc1[nt], aH[ks], bh);
                mma_bf16(acc1[nt], aH[ks], bl);
                mma_bf16(acc1[nt], aL[ks], bh);
            }
        }

        // ---- pack H fragments (relu fused); acc1 dies here ----
        uint32_t hA[8][4], lA[8][4];
        #pragma unroll
        for (int ks = 0; ks < 8; ks++) {
            float v00 = fmaxf(acc1[2 * ks][0], 0.f);
            float v01 = fmaxf(acc1[2 * ks][1], 0.f);
            float v02 = fmaxf(acc1[2 * ks][2], 0.f);
            float v03 = fmaxf(acc1[2 * ks][3], 0.f);
            float v10 = fmaxf(acc1[2 * ks + 1][0], 0.f);
            float v11 = fmaxf(acc1[2 * ks + 1][1], 0.f);
            float v12 = fmaxf(acc1[2 * ks + 1][2], 0.f);
            float v13 = fmaxf(acc1[2 * ks + 1][3], 0.f);
            split_pair(v00, v01, hA[ks][0], lA[ks][0]);
            split_pair(v02, v03, hA[ks][1], lA[ks][1]);
            split_pair(v10, v11, hA[ks][2], lA[ks][2]);
            split_pair(v12, v13, hA[ks][3], lA[ks][3]);
        }

        // ---- GEMM2: acc2 = H @ W2 (K=128), literal offsets ----
        float acc2[8][4];
        #pragma unroll
        for (int nt = 0; nt < 8; nt++)
            #pragma unroll
            for (int j = 0; j < 4; j++) acc2[nt][j] = 0.f;

        #pragma unroll
        for (int ks = 0; ks < 8; ks++) {
            #pragma unroll
            for (int nt = 0; nt < 8; nt++) {
                uint4 B = *(const uint4*)(pB2 + ks * 4096 + nt * 512);
                uint32_t bh[2] = {B.x, B.y}, bl[2] = {B.z, B.w};
                mma_bf16(acc2[nt], hA[ks], bh);
                mma_bf16(acc2[nt], hA[ks], bl);
                mma_bf16(acc2[nt], lA[ks], bh);
            }
        }

        // ---- stage D2 into sA (XOR chunk layout, natural slot order) ----
        #pragma unroll
        for (int nt = 0; nt < 8; nt++) {
            int c = 2 * nt + (qt >> 1), s = qt & 1;
            {
                int r = mrow0;
                uint32_t a = (uint32_t)(r << 8) + ((uint32_t)((c ^ (r & 15)) & 15) << 4)
                           + ((uint32_t)s << 3);
                *(float2*)(smc + E_SA + a) = make_float2(acc2[nt][0], acc2[nt][1]);
            }
            {
                int r = mrow0 + 8;
                uint32_t a = (uint32_t)(r << 8) + ((uint32_t)((c ^ (r & 15)) & 15) << 4)
                           + ((uint32_t)s << 3);
                *(float2*)(smc + E_SA + a) = make_float2(acc2[nt][2], acc2[nt][3]);
            }
        }
        __syncthreads();

        // ---- coalesced epilogue: red.v4 agg; dst = ea + (D2 + b2) ----
        {
            const float4* easrc = (const float4*)(ea + (size_t)i0 * DD);
            float4* dstp = (float4*)(dst + (size_t)i0 * DD);
            #pragma unroll
            for (int p = 0; p < 8; p++) {
                int id = p * 256 + tid;
                int row = id >> 4, c = id & 15;
                uint4 d = *(const uint4*)(smc + E_SA + (row << 8)
                                          + (((c ^ (row & 15)) & 15) << 4));
                float4 v;
                v.x = __uint_as_float(d.x) + sb2[4 * c + 0];
                v.y = __uint_as_float(d.y) + sb2[4 * c + 1];
                v.z = __uint_as_float(d.z) + sb2[4 * c + 2];
                v.w = __uint_as_float(d.w) + sb2[4 * c + 3];
                float* ap = agg + (size_t)sRows[row] * DD + 4 * c;
                asm volatile("red.global.add.v4.f32 [%0], {%1, %2, %3, %4};"
                             :: "l"(ap), "f"(v.x), "f"(v.y), "f"(v.z), "f"(v.w)
                             : "memory");
                float4 e = easrc[id];
                float4 o = make_float4(e.x + v.x, e.y + v.y, e.z + v.z, e.w + v.w);
                dstp[id] = o;
            }
        }
        __syncthreads();   // D2 reads done before next tile's raw copy
    }
}

// ---------------- node / px kernels (round-12, known good) -----------------
#define OFF_AH   0
#define OFF_AL   34816
#define OFF_W1H  69632
#define OFF_W1L  104448
#define OFF_W2H  139264
#define OFF_W2L  156672
#define OFF_B1   174080
#define OFF_B2   174592
#define SMEMSZ   175360

__global__ void __launch_bounds__(256, 1)
px_k(const float* __restrict__ x, const float* __restrict__ Wc,
     const float* __restrict__ be1, float* __restrict__ Px)
{
    extern __shared__ char smc[];
    uint16_t* sAh = (uint16_t*)(smc + OFF_AH);
    uint16_t* sAl = (uint16_t*)(smc + OFF_AL);
    uint16_t* sWh = (uint16_t*)(smc + OFF_W1H);
    uint16_t* sWl = (uint16_t*)(smc + OFF_W1L);
    float*    sb1 = (float*)(smc + OFF_B1);

    const int tid = threadIdx.x;
    const int lane = tid & 31, w = tid >> 5;
    const int g = lane >> 2, qt = lane & 3;
    const int wm = w >> 1, wn = w & 1;

    {
        int n = tid & 127, k0 = (tid >> 7) * 32;
        for (int k = k0; k < k0 + 32; k += 2) {
            uint32_t hi, lo;
            split_pair(Wc[k * 128 + n], Wc[(k + 1) * 128 + n], hi, lo);
            *(uint32_t*)&sWh[n * KP + k] = hi;
            *(uint32_t*)&sWl[n * KP + k] = lo;
        }
    }
    if (tid < 128) sb1[tid] = be1[tid];
    __syncthreads();

    for (int tile = blockIdx.x; tile < NT; tile += gridDim.x) {
        const int i0 = tile * 128;
        {
            const int m = tid & 127, ch = (tid >> 7) * 32;
            const int gi = i0 + m;
            const bool valid = gi < NN;
            const float* src = x + (size_t)(valid ? gi : 0) * DD + ch;
            #pragma unroll
            for (int c = 0; c < 32; c += 8) {
                float4 f0, f1;
                if (valid) { f0 = *(const float4*)(src + c); f1 = *(const float4*)(src + c + 4); }
                else { f0 = make_float4(0,0,0,0); f1 = f0; }
                uint32_t hw[4], lw[4];
                split_pair(f0.x, f0.y, hw[0], lw[0]);
                split_pair(f0.z, f0.w, hw[1], lw[1]);
                split_pair(f1.x, f1.y, hw[2], lw[2]);
                split_pair(f1.z, f1.w, hw[3], lw[3]);
                int e = m * KP + ch + c;
                *(uint4*)&sAh[e] = *(uint4*)hw;
                *(uint4*)&sAl[e] = *(uint4*)lw;
            }
        }
        __syncthreads();

        float acc[2][8][4];
        #pragma unroll
        for (int mt = 0; mt < 2; mt++)
            #pragma unroll
            for (int nt = 0; nt < 8; nt++)
                #pragma unroll
                for (int j = 0; j < 4; j++) acc[mt][nt][j] = 0.f;

        #pragma unroll
        for (int ks = 0; ks < 4; ks++) {
            const int kb = ks * 16 + 2 * qt;
            uint32_t ah[2][4], al[2][4];
            #pragma unroll
            for (int mt = 0; mt < 2; mt++) {
                int e = (wm * 32 + mt * 16 + g) * KP + kb;
                ah[mt][0] = *(const uint32_t*)&sAh[e];
                ah[mt][1] = *(const uint32_t*)&sAh[e + 8 * KP];
                ah[mt][2] = *(const uint32_t*)&sAh[e + 8];
                ah[mt][3] = *(const uint32_t*)&sAh[e + 8 * KP + 8];
                al[mt][0] = *(const uint32_t*)&sAl[e];
                al[mt][1] = *(const uint32_t*)&sAl[e + 8 * KP];
                al[mt][2] = *(const uint32_t*)&sAl[e + 8];
                al[mt][3] = *(const uint32_t*)&sAl[e + 8 * KP + 8];
            }
            #pragma unroll
            for (int nt = 0; nt < 8; nt++) {
                int e = (wn * 64 + nt * 8 + g) * KP + kb;
                uint32_t bh[2], bl[2];
                bh[0] = *(const uint32_t*)&sWh[e];
                bh[1] = *(const uint32_t*)&sWh[e + 8];
                bl[0] = *(const uint32_t*)&sWl[e];
                bl[1] = *(const uint32_t*)&sWl[e + 8];
                mma_bf16(acc[0][nt], ah[0], bh);
                mma_bf16(acc[1][nt], ah[1], bh);
                mma_bf16(acc[0][nt], ah[0], bl);
                mma_bf16(acc[1][nt], ah[1], bl);
                mma_bf16(acc[0][nt], al[0], bh);
                mma_bf16(acc[1][nt], al[1], bh);
            }
        }

        #pragma unroll
        for (int mt = 0; mt < 2; mt++)
            #pragma unroll
            for (int nt = 0; nt < 8; nt++) {
                int rl = wm * 32 + mt * 16 + g;
                int col = wn * 64 + nt * 8 + 2 * qt;
                #pragma unroll
                for (int rh = 0; rh < 2; rh++) {
                    int gi = i0 + rl + rh * 8;
                    if (gi >= NN) continue;
                    float2 v = make_float2(acc[mt][nt][rh * 2] + sb1[col],
                                           acc[mt][nt][rh * 2 + 1] + sb1[col + 1]);
                    *(float2*)&Px[(size_t)gi * 128 + col] = v;
                }
            }
        __syncthreads();
    }
}

__global__ void __launch_bounds__(256, 1)
node_mma(const float* __restrict__ x_src, const float* __restrict__ a_src,
         const float* __restrict__ W1, const float* __restrict__ b1,
         const float* __restrict__ W2, const float* __restrict__ b2,
         float* __restrict__ dst, const float* __restrict__ inv, int count)
{
    extern __shared__ char smc[];
    uint16_t* sAh  = (uint16_t*)(smc + OFF_AH);
    uint16_t* sAl  = (uint16_t*)(smc + OFF_AL);
    uint16_t* sW1h = (uint16_t*)(smc + OFF_W1H);
    uint16_t* sW1l = (uint16_t*)(smc + OFF_W1L);
    uint16_t* sW2h = (uint16_t*)(smc + OFF_W2H);
    uint16_t* sW2l = (uint16_t*)(smc + OFF_W2L);
    float*    sb1  = (float*)(smc + OFF_B1);
    float*    sb2  = (float*)(smc + OFF_B2);

    const int tid = threadIdx.x;
    const int lane = tid & 31, w = tid >> 5;
    const int g = lane >> 2, qt = lane & 3;
    const int wm = w >> 1, wn = w & 1;

    {
        int n = tid & 127, k0 = (tid >> 7) * 64;
        for (int k = k0; k < k0 + 64; k += 2) {
            uint32_t hi, lo;
            split_pair(W1[k * 128 + n], W1[(k + 1) * 128 + n], hi, lo);
            *(uint32_t*)&sW1h[n * KP + k] = hi;
            *(uint32_t*)&sW1l[n * KP + k] = lo;
        }
    }
    {
        int n = tid & 63, k0 = (tid >> 6) * 32;
        for (int k = k0; k < k0 + 32; k += 2) {
            uint32_t hi, lo;
            split_pair(W2[k * 64 + n], W2[(k + 1) * 64 + n], hi, lo);
            *(uint32_t*)&sW2h[n * KP + k] = hi;
            *(uint32_t*)&sW2l[n * KP + k] = lo;
        }
    }
    if (tid < 128) sb1[tid] = b1[tid];
    if (tid < 64)  sb2[tid] = b2[tid];
    __syncthreads();

    for (int tile = blockIdx.x; tile < NT; tile += gridDim.x) {
        const int i0 = tile * 128;
        {
            const int m = tid & 127, half = tid >> 7;
            const int gi = i0 + m;
            const bool valid = gi < count;
            const float* src;
            float scale = 1.0f;
            bool doscale = false;
            if (half == 0) {
                src = x_src + (size_t)(valid ? gi : 0) * DD;
            } else {
                src = a_src + (size_t)(valid ? gi : 0) * DD;
                scale = valid ? inv[gi] : 0.0f;
                doscale = true;
            }
            #pragma unroll
            for (int c = 0; c < 64; c += 8) {
                float4 f0 = *(const float4*)(src + c);
                float4 f1 = *(const float4*)(src + c + 4);
                if (doscale) {
                    f0.x *= scale; f0.y *= scale; f0.z *= scale; f0.w *= scale;
                    f1.x *= scale; f1.y *= scale; f1.z *= scale; f1.w *= scale;
                }
                uint32_t hw[4], lw[4];
                split_pair(f0.x, f0.y, hw[0], lw[0]);
                split_pair(f0.z, f0.w, hw[1], lw[1]);
                split_pair(f1.x, f1.y, hw[2], lw[2]);
                split_pair(f1.z, f1.w, hw[3], lw[3]);
                int e = m * KP + half * 64 + c;
                *(uint4*)&sAh[e] = *(uint4*)hw;
                *(uint4*)&sAl[e] = *(uint4*)lw;
            }
        }
        __syncthreads();

        float acc[2][8][4];
        #pragma unroll
        for (int mt = 0; mt < 2; mt++)
            #pragma unroll
            for (int nt = 0; nt < 8; nt++)
                #pragma unroll
                for (int j = 0; j < 4; j++) acc[mt][nt][j] = 0.f;

        #pragma unroll
        for (int ks = 0; ks < 8; ks++) {
            const int kb = ks * 16 + 2 * qt;
            uint32_t ah[2][4], al[2][4];
            #pragma unroll
            for (int mt = 0; mt < 2; mt++) {
                int e = (wm * 32 + mt * 16 + g) * KP + kb;
                ah[mt][0] = *(const uint32_t*)&sAh[e];
                ah[mt][1] = *(const uint32_t*)&sAh[e + 8 * KP];
                ah[mt][2] = *(const uint32_t*)&sAh[e + 8];
                ah[mt][3] = *(const uint32_t*)&sAh[e + 8 * KP + 8];
                al[mt][0] = *(const uint32_t*)&sAl[e];
                al[mt][1] = *(const uint32_t*)&sAl[e + 8 * KP];
                al[mt][2] = *(const uint32_t*)&sAl[e + 8];
                al[mt][3] = *(const uint32_t*)&sAl[e + 8 * KP + 8];
            }
            #pragma unroll
            for (int nt = 0; nt < 8; nt++) {
                int e = (wn * 64 + nt * 8 + g) * KP + kb;
                uint32_t bh[2], bl[2];
                bh[0] = *(const uint32_t*)&sW1h[e];
                bh[1] = *(const uint32_t*)&sW1h[e + 8];
                bl[0] = *(const uint32_t*)&sW1l[e];
                bl[1] = *(const uint32_t*)&sW1l[e + 8];
                mma_bf16(acc[0][nt], ah[0], bh);
                mma_bf16(acc[1][nt], ah[1], bh);
                mma_bf16(acc[0][nt], ah[0], bl);
                mma_bf16(acc[1][nt], ah[1], bl);
                mma_bf16(acc[0][nt], al[0], bh);
                mma_bf16(acc[1][nt], al[1], bh);
            }
        }
        __syncthreads();

        #pragma unroll
        for (int mt = 0; mt < 2; mt++)
            #pragma unroll
            for (int nt = 0; nt < 8; nt++) {
                int row = wm * 32 + mt * 16 + g;
                int col = wn * 64 + nt * 8 + 2 * qt;
                float v0 = fmaxf(acc[mt][nt][0] + sb1[col], 0.f);
                float v1 = fmaxf(acc[mt][nt][1] + sb1[col + 1], 0.f);
                float v2 = fmaxf(acc[mt][nt][2] + sb1[col], 0.f);
                float v3 = fmaxf(acc[mt][nt][3] + sb1[col + 1], 0.f);
                uint32_t hi, lo;
                split_pair(v0, v1, hi, lo);
                *(uint32_t*)&sAh[row * KP + col] = hi;
                *(uint32_t*)&sAl[row * KP + col] = lo;
                split_pair(v2, v3, hi, lo);
                *(uint32_t*)&sAh[(row + 8) * KP + col] = hi;
                *(uint32_t*)&sAl[(row + 8) * KP + col] = lo;
            }
        __syncthreads();

        float acc2[2][4][4];
        #pragma unroll
        for (int mt = 0; mt < 2; mt++)
            #pragma unroll
            for (int nt = 0; nt < 4; nt++)
                #pragma unroll
                for (int j = 0; j < 4; j++) acc2[mt][nt][j] = 0.f;

        #pragma unroll
        for (int ks = 0; ks < 8; ks++) {
            const int kb = ks * 16 + 2 * qt;
            uint32_t ah[2][4], al[2][4];
            #pragma unroll
            for (int mt = 0; mt < 2; mt++) {
                int e = (wm * 32 + mt * 16 + g) * KP + kb;
                ah[mt][0] = *(const uint32_t*)&sAh[e];
                ah[mt][1] = *(const uint32_t*)&sAh[e + 8 * KP];
                ah[mt][2] = *(const uint32_t*)&sAh[e + 8];
                ah[mt][3] = *(const uint32_t*)&sAh[e + 8 * KP + 8];
                al[mt][0] = *(const uint32_t*)&sAl[e];
                al[mt][1] = *(const uint32_t*)&sAl[e + 8 * KP];
                al[mt][2] = *(const uint32_t*)&sAl[e + 8];
                al[mt][3] = *(const uint32_t*)&sAl[e + 8 * KP + 8];
            }
            #pragma unroll
            for (int nt = 0; nt < 4; nt++) {
                int e = (wn * 32 + nt * 8 + g) * KP + kb;
                uint32_t bh[2], bl[2];
                bh[0] = *(const uint32_t*)&sW2h[e];
                bh[1] = *(const uint32_t*)&sW2h[e + 8];
                bl[0] = *(const uint32_t*)&sW2l[e];
                bl[1] = *(const uint32_t*)&sW2l[e + 8];
                mma_bf16(acc2[0][nt], ah[0], bh);
                mma_bf16(acc2[1][nt], ah[1], bh);
                mma_bf16(acc2[0][nt], ah[0], bl);
                mma_bf16(acc2[1][nt], ah[1], bl);
                mma_bf16(acc2[0][nt], al[0], bh);
                mma_bf16(acc2[1][nt], al[1], bh);
            }
        }

        #pragma unroll
        for (int mt = 0; mt < 2; mt++)
            #pragma unroll
            for (int nt = 0; nt < 4; nt++) {
                int rl = wm * 32 + mt * 16 + g;
                int col = wn * 32 + nt * 8 + 2 * qt;
                #pragma unroll
                for (int rh = 0; rh < 2; rh++) {
                    int row = rl + rh * 8;
                    int gi = i0 + row;
                    if (gi >= count) continue;
                    float vx = acc2[mt][nt][rh * 2 + 0] + sb2[col];
                    float vy = acc2[mt][nt][rh * 2 + 1] + sb2[col + 1];
                    float2 rv = *(const float2*)(x_src + (size_t)gi * DD + col);
                    *(float2*)(dst + (size_t)gi * DD + col) =
                        make_float2(rv.x + vx, rv.y + vy);
                }
            }
        __syncthreads();
    }
}

extern "C" void kernel_launch(void* const* d_in, const int* in_sizes, int n_in,
                              void* d_out, int out_size)
{
    const float* x   = (const float*)d_in[0];
    const float* ea  = (const float*)d_in[1];
    const float* We1 = (const float*)d_in[2];
    const float* be1 = (const float*)d_in[3];
    const float* We2 = (const float*)d_in[4];
    const float* be2 = (const float*)d_in[5];
    const float* Wn1 = (const float*)d_in[6];
    const float* bn1 = (const float*)d_in[7];
    const float* Wn2 = (const float*)d_in[8];
    const float* bn2 = (const float*)d_in[9];
    const void*  eidx = d_in[10];

    float* out_x  = (float*)d_out;
    float* out_ea = (float*)d_out + (size_t)NN * DD;

    float *agg, *agg2, *inv, *Wc, *Px;
    int* cnt;
    cudaGetSymbolAddress((void**)&agg,  g_agg);
    cudaGetSymbolAddress((void**)&agg2, g_agg2);
    cudaGetSymbolAddress((void**)&inv,  g_inv);
    cudaGetSymbolAddress((void**)&cnt,  g_cnt);
    cudaGetSymbolAddress((void**)&Wc,   g_Wc);
    cudaGetSymbolAddress((void**)&Px,   g_Px);

    cudaFuncSetAttribute(edge_mma, cudaFuncAttributeMaxDynamicSharedMemorySize, E_SMEM);
    cudaFuncSetAttribute(node_mma, cudaFuncAttributeMaxDynamicSharedMemorySize, SMEMSZ);
    cudaFuncSetAttribute(px_k,     cudaFuncAttributeMaxDynamicSharedMemorySize, SMEMSZ);

    int smcount = 148;
    cudaDeviceGetAttribute(&smcount, cudaDevAttrMultiProcessorCount, 0);
    int ge = 2 * smcount < ET ? 2 * smcount : ET;
    int gn = smcount < NT ? smcount : NT;

    // Edge kernel stays at my launch index 3 (profiled by ncu -s 5 -c 1).
    prolog_k<<<(NN * DD / 4 + 255) / 256, 256>>>(eidx, agg, agg2, cnt);      // 0
    combine_count_k<<<(EE + 255) / 256, 256>>>(We1, Wc, eidx, cnt);          // 1
    px_k<<<gn, 256, SMEMSZ>>>(x, Wc, be1, Px);                               // 2
    edge_mma<<<ge, 256, E_SMEM>>>(ea, eidx, Px, Wc, We2, be2,                // 3 <- profiled
                                  out_ea, agg, ET);
    inv_k<<<(NN + 255) / 256, 256>>>(cnt, inv);                              // 4
    node_mma<<<gn, 256, SMEMSZ>>>(x, agg, Wn1, bn1, Wn2, bn2,                // 5
                                  out_x, inv, NN);

    // iteration 2 (agg2 pre-zeroed in prolog -> no mid-stream zero pass)
    px_k<<<gn, 256, SMEMSZ>>>(out_x, Wc, be1, Px);                           // 6
    edge_mma<<<ge, 256, E_SMEM>>>(out_ea, eidx, Px, Wc, We2, be2,            // 7
                                  out_ea, agg2, ET);
    node_mma<<<gn, 256, SMEMSZ>>>(out_x, agg2, Wn1, bn1, Wn2, bn2,           // 8
                                  out_x, inv, NN);
}